// round 2
// baseline (speedup 1.0000x reference)
#include <cuda_runtime.h>
#include <math.h>

#define LV 2048
#define LT 512
#define LTOT 2560
#define D 512
#define H 8
#define DK 64
#define FF 1024

// ---------------- scratch (static device allocations are permitted) ----------------
__device__ float g_mask[(size_t)LV * LV];        // 16.8 MB
__device__ float g_partial[LV];
__device__ float g_src[(size_t)LTOT * D];        // residual stream
__device__ float g_src2[(size_t)LTOT * D];       // normed stream
__device__ float g_posq[(size_t)LV * D];
__device__ float g_qin[(size_t)LV * D];
__device__ float g_kin[(size_t)LV * D];
__device__ float g_qh[(size_t)LV * D];
__device__ float g_kh[(size_t)LV * D];
__device__ float g_vh[(size_t)LV * D];
__device__ float g_S[(size_t)H * LV * LV];       // 134 MB attention scores
__device__ float g_att[(size_t)LV * D];
__device__ float g_proj[(size_t)LTOT * D];
__device__ float g_ffn[(size_t)LTOT * FF];

// ---------------- block reductions (blockDim.x == 256) ----------------
__device__ __forceinline__ float blk_sum(float v, float* sh) {
    int lane = threadIdx.x & 31, wid = threadIdx.x >> 5;
#pragma unroll
    for (int o = 16; o; o >>= 1) v += __shfl_xor_sync(0xffffffffu, v, o);
    if (lane == 0) sh[wid] = v;
    __syncthreads();
    if (threadIdx.x < 32) {
        float t = (threadIdx.x < 8) ? sh[threadIdx.x] : 0.f;
#pragma unroll
        for (int o = 4; o; o >>= 1) t += __shfl_xor_sync(0xffffffffu, t, o);
        if (threadIdx.x == 0) sh[0] = t;
    }
    __syncthreads();
    float r = sh[0];
    __syncthreads();
    return r;
}

__device__ __forceinline__ float blk_max(float v, float* sh) {
    int lane = threadIdx.x & 31, wid = threadIdx.x >> 5;
#pragma unroll
    for (int o = 16; o; o >>= 1) v = fmaxf(v, __shfl_xor_sync(0xffffffffu, v, o));
    if (lane == 0) sh[wid] = v;
    __syncthreads();
    if (threadIdx.x < 32) {
        float t = (threadIdx.x < 8) ? sh[threadIdx.x] : -3.4e38f;
#pragma unroll
        for (int o = 4; o; o >>= 1) t = fmaxf(t, __shfl_xor_sync(0xffffffffu, t, o));
        if (threadIdx.x == 0) sh[0] = t;
    }
    __syncthreads();
    float r = sh[0];
    __syncthreads();
    return r;
}

// ---------------- mask + sparsity-loss partials ----------------
__global__ void k_mask(const float* __restrict__ learn) {
    int n = blockIdx.x;
    __shared__ float sh[32];
    const float L2G = -0.15200309344504997f; // log2(0.9)
    float psum = 0.f;
    for (int m = threadIdx.x; m < LV; m += 256) {
        float lw = learn[(size_t)n * LV + m];
        float sig = 1.f / (1.f + expf(-lw));
        float maskv;
        if (m == n) {
            maskv = 1.f;
        } else if (n > m) {
            maskv = exp2f((float)(n - m) * L2G) * sig;
            psum += sig;
        } else {
            maskv = 0.f;
            psum += sig;
        }
        g_mask[(size_t)n * LV + m] = maskv;
    }
    float t = blk_sum(psum, sh);
    if (threadIdx.x == 0) g_partial[n] = t;
}

__global__ void k_loss(float* out, int out_size) {
    __shared__ float sh[32];
    float s = 0.f;
    for (int i = threadIdx.x; i < LV; i += 256) s += g_partial[i];
    s = blk_sum(s, sh);
    if (threadIdx.x == 0 && out_size > LV * D + LT * D)
        out[(size_t)LV * D + (size_t)LT * D] = s / ((float)LV * (float)LV);
}

// ---------------- concat + LN1 ----------------
__global__ void k_ln1(const float* __restrict__ vid, const float* __restrict__ txt,
                      const float* __restrict__ w, const float* __restrict__ b) {
    int r = blockIdx.x;
    const float* x = (r < LV) ? (vid + (size_t)r * D) : (txt + (size_t)(r - LV) * D);
    __shared__ float sh[32];
    int i0 = threadIdx.x, i1 = threadIdx.x + 256;
    float v0 = x[i0], v1 = x[i1];
    float s = blk_sum(v0 + v1, sh);
    float s2 = blk_sum(v0 * v0 + v1 * v1, sh);
    float mu = s * (1.f / D);
    float var = s2 * (1.f / D) - mu * mu;
    float inv = rsqrtf(var + 1e-5f);
    size_t o = (size_t)r * D;
    g_src[o + i0] = v0;
    g_src[o + i1] = v1;
    g_src2[o + i0] = (v0 - mu) * inv * w[i0] + b[i0];
    g_src2[o + i1] = (v1 - mu) * inv * w[i1] + b[i1];
}

// ---------------- xpos positional encodings + q/k inputs ----------------
__global__ void k_pos(const float* __restrict__ vid) {
    int r = blockIdx.x;   // row 0..2047
    int j = threadIdx.x;  // pair 0..255
    const float L2_1E4 = 13.287712379549449f; // log2(10000)
    float sj = (2.f * (float)j + 204.8f) / 716.8f;
    float scale = exp2f(((float)r / 512.f) * log2f(sj));
    float invf = exp2f(-((float)j / 256.f) * L2_1E4);
    float ang = (float)r * invf;
    float sn, cs;
    sincosf(ang, &sn, &cs);
    size_t o = (size_t)r * D + 2 * j;
    float x0 = vid[o], x1 = vid[o + 1];
    float cq = cs * scale, sq = sn * scale;
    float pq0 = x0 * cq - x1 * sq;
    float pq1 = x1 * cq + x0 * sq;
    float iscale = 1.f / scale;
    float ck = cs * iscale, sk = sn * iscale;
    float pk0 = x0 * ck - x1 * sk;
    float pk1 = x1 * ck + x0 * sk;
    g_posq[o] = pq0; g_posq[o + 1] = pq1;
    float n0 = g_src2[o], n1 = g_src2[o + 1];
    g_qin[o] = n0 + pq0; g_qin[o + 1] = n1 + pq1;
    g_kin[o] = n0 + pk0; g_kin[o + 1] = n1 + pk1;
}

// ---------------- generic tiled SGEMM body: C = alpha*(A(MxK) @ B(NxK)^T + bias), opt GELU ----------------
__device__ __forceinline__ void gemm_body(const float* __restrict__ A, const float* __restrict__ B,
                                          const float* __restrict__ bias, float* __restrict__ C,
                                          int M, int N, int K, float alpha, int act) {
    const int BM = 64, BN = 64, BK = 16;
    __shared__ float As[BK][BM + 4];
    __shared__ float Bs[BK][BN + 4];
    int bm = blockIdx.y * BM, bn = blockIdx.x * BN;
    int tx = threadIdx.x & 15, ty = threadIdx.x >> 4;
    float acc[4][4] = {};
    for (int k0 = 0; k0 < K; k0 += BK) {
        for (int i = threadIdx.x; i < BM * BK; i += 256) {
            int row = i >> 4, kk = i & 15;
            As[kk][row] = A[(size_t)(bm + row) * K + k0 + kk];
        }
        for (int i = threadIdx.x; i < BN * BK; i += 256) {
            int row = i >> 4, kk = i & 15;
            Bs[kk][row] = B[(size_t)(bn + row) * K + k0 + kk];
        }
        __syncthreads();
#pragma unroll
        for (int kk = 0; kk < BK; kk++) {
            float a[4], bb[4];
#pragma unroll
            for (int i = 0; i < 4; i++) a[i] = As[kk][ty * 4 + i];
#pragma unroll
            for (int jj = 0; jj < 4; jj++) bb[jj] = Bs[kk][tx * 4 + jj];
#pragma unroll
            for (int i = 0; i < 4; i++)
#pragma unroll
                for (int jj = 0; jj < 4; jj++)
                    acc[i][jj] = fmaf(a[i], bb[jj], acc[i][jj]);
        }
        __syncthreads();
    }
#pragma unroll
    for (int i = 0; i < 4; i++) {
        int row = bm + ty * 4 + i;
#pragma unroll
        for (int jj = 0; jj < 4; jj++) {
            int col = bn + tx * 4 + jj;
            float v = (acc[i][jj] + bias[col]) * alpha;
            if (act) v = 0.5f * v * (1.f + erff(v * 0.70710678118654752f));
            C[(size_t)row * N + col] = v;
        }
    }
}

__global__ void k_gemm_q(const float* w, const float* b) { gemm_body(g_qin, w, b, g_qh, LV, D, D, 0.125f, 0); }
__global__ void k_gemm_k(const float* w, const float* b) { gemm_body(g_kin, w, b, g_kh, LV, D, D, 1.f, 0); }
__global__ void k_gemm_v(const float* w, const float* b) { gemm_body(g_src2, w, b, g_vh, LV, D, D, 1.f, 0); }
__global__ void k_gemm_o(const float* w, const float* b) { gemm_body(g_att, w, b, g_proj, LV, D, D, 1.f, 0); }
__global__ void k_gemm_f1(const float* w, const float* b) { gemm_body(g_src2, w, b, g_ffn, LTOT, FF, D, 1.f, 1); }
__global__ void k_gemm_f2(const float* w, const float* b) { gemm_body(g_ffn, w, b, g_proj, LTOT, D, FF, 1.f, 0); }

// ---------------- attention scores (QK^T * mask) ----------------
__global__ void k_scores() {
    int h = blockIdx.z;
    int bm = blockIdx.y * 64, bn = blockIdx.x * 64;
    __shared__ float Qs[64][65];
    __shared__ float Ks[64][65];
    for (int i = threadIdx.x; i < 64 * 64; i += 256) {
        int row = i >> 6, k = i & 63;
        Qs[row][k] = g_qh[(size_t)(bm + row) * D + h * DK + k];
        Ks[row][k] = g_kh[(size_t)(bn + row) * D + h * DK + k];
    }
    __syncthreads();
    int tx = threadIdx.x & 15, ty = threadIdx.x >> 4;
    float acc[4][4] = {};
#pragma unroll 8
    for (int kk = 0; kk < 64; kk++) {
        float a[4], bb[4];
#pragma unroll
        for (int i = 0; i < 4; i++) a[i] = Qs[ty * 4 + i][kk];
#pragma unroll
        for (int jj = 0; jj < 4; jj++) bb[jj] = Ks[tx * 4 + jj][kk];
#pragma unroll
        for (int i = 0; i < 4; i++)
#pragma unroll
            for (int jj = 0; jj < 4; jj++)
                acc[i][jj] = fmaf(a[i], bb[jj], acc[i][jj]);
    }
#pragma unroll
    for (int i = 0; i < 4; i++) {
        int n = bm + ty * 4 + i;
#pragma unroll
        for (int jj = 0; jj < 4; jj++) {
            int m = bn + tx * 4 + jj;
            g_S[((size_t)h * LV + n) * LV + m] = acc[i][jj] * g_mask[(size_t)n * LV + m];
        }
    }
}

// ---------------- row softmax over 2048 ----------------
__global__ void k_softmax() {
    int n = blockIdx.x, h = blockIdx.y;
    float* row = g_S + ((size_t)h * LV + n) * LV;
    __shared__ float sh[32];
    float v[8];
    float mx = -3.4e38f;
#pragma unroll
    for (int t = 0; t < 8; t++) {
        v[t] = row[threadIdx.x + t * 256];
        mx = fmaxf(mx, v[t]);
    }
    mx = blk_max(mx, sh);
    float s = 0.f;
#pragma unroll
    for (int t = 0; t < 8; t++) {
        v[t] = expf(v[t] - mx);
        s += v[t];
    }
    s = blk_sum(s, sh);
    float inv = 1.f / s;
#pragma unroll
    for (int t = 0; t < 8; t++) row[threadIdx.x + t * 256] = v[t] * inv;
}

// ---------------- attn @ V ----------------
__global__ void k_av() {
    int h = blockIdx.y;
    int bm = blockIdx.x * 64;
    __shared__ float Ps[64][65];
    __shared__ float Vs[64][65];
    int tx = threadIdx.x & 15, ty = threadIdx.x >> 4;
    float acc[4][4] = {};
    for (int m0 = 0; m0 < LV; m0 += 64) {
        for (int i = threadIdx.x; i < 64 * 64; i += 256) {
            int r = i >> 6, c = i & 63;
            Ps[r][c] = g_S[((size_t)h * LV + bm + r) * LV + m0 + c];
            Vs[r][c] = g_vh[(size_t)(m0 + r) * D + h * DK + c];
        }
        __syncthreads();
#pragma unroll 8
        for (int kk = 0; kk < 64; kk++) {
            float a[4], bb[4];
#pragma unroll
            for (int i = 0; i < 4; i++) a[i] = Ps[ty * 4 + i][kk];
#pragma unroll
            for (int jj = 0; jj < 4; jj++) bb[jj] = Vs[kk][tx * 4 + jj];
#pragma unroll
            for (int i = 0; i < 4; i++)
#pragma unroll
                for (int jj = 0; jj < 4; jj++)
                    acc[i][jj] = fmaf(a[i], bb[jj], acc[i][jj]);
        }
        __syncthreads();
    }
#pragma unroll
    for (int i = 0; i < 4; i++)
#pragma unroll
        for (int jj = 0; jj < 4; jj++)
            g_att[(size_t)(bm + ty * 4 + i) * D + h * DK + tx * 4 + jj] = acc[i][jj];
}

// ---------------- residual + pos + LN2 ----------------
__device__ __forceinline__ float sine_pos_elem(float xe, int i) {
    const float L2_1E4 = 13.287712379549449f;
    int j = i >> 1;
    float dim = exp2f(((float)j / 256.f) * L2_1E4);
    float val = xe / dim;
    return (i & 1) ? cosf(val) : sinf(val);
}

__global__ void k_res_ln2(const float* __restrict__ w, const float* __restrict__ b) {
    int r = blockIdx.x;
    __shared__ float sh[32];
    int i0 = threadIdx.x, i1 = threadIdx.x + 256;
    size_t o = (size_t)r * D;
    float v0, v1;
    if (r < LV) {
        v0 = g_src[o + i0] + g_proj[o + i0] + g_posq[o + i0];
        v1 = g_src[o + i1] + g_proj[o + i1] + g_posq[o + i1];
    } else {
        int t = r - LV;
        float xe = (float)(t + 1) / (512.f + 1e-6f) * 6.283185307179586f;
        v0 = g_src[o + i0] + g_src2[o + i0] + sine_pos_elem(xe, i0);
        v1 = g_src[o + i1] + g_src2[o + i1] + sine_pos_elem(xe, i1);
    }
    float s = blk_sum(v0 + v1, sh);
    float s2 = blk_sum(v0 * v0 + v1 * v1, sh);
    float mu = s * (1.f / D);
    float var = s2 * (1.f / D) - mu * mu;
    float inv = rsqrtf(var + 1e-5f);
    g_src[o + i0] = v0;
    g_src[o + i1] = v1;
    g_src2[o + i0] = (v0 - mu) * inv * w[i0] + b[i0];
    g_src2[o + i1] = (v1 - mu) * inv * w[i1] + b[i1];
}

// ---------------- residual + LN3 + output ----------------
__global__ void k_res_ln3(const float* __restrict__ w, const float* __restrict__ b,
                          float* __restrict__ out) {
    int r = blockIdx.x;
    __shared__ float sh[32];
    int i0 = threadIdx.x, i1 = threadIdx.x + 256;
    size_t o = (size_t)r * D;
    float v0 = g_src[o + i0] + g_proj[o + i0];
    float v1 = g_src[o + i1] + g_proj[o + i1];
    float s = blk_sum(v0 + v1, sh);
    float s2 = blk_sum(v0 * v0 + v1 * v1, sh);
    float mu = s * (1.f / D);
    float var = s2 * (1.f / D) - mu * mu;
    float inv = rsqrtf(var + 1e-5f);
    // vid block rows 0..LV-1 then txt rows follow contiguously -> same flat offset
    out[o + i0] = (v0 - mu) * inv * w[i0] + b[i0];
    out[o + i1] = (v1 - mu) * inv * w[i1] + b[i1];
}

extern "C" void kernel_launch(void* const* d_in, const int* in_sizes, int n_in,
                              void* d_out, int out_size) {
    const float* src_vid = (const float*)d_in[0];
    const float* src_txt = (const float*)d_in[1];
    const float* ln1_w = (const float*)d_in[2];
    const float* ln1_b = (const float*)d_in[3];
    const float* wq = (const float*)d_in[4];
    const float* bq = (const float*)d_in[5];
    const float* wk = (const float*)d_in[6];
    const float* bk = (const float*)d_in[7];
    const float* wv = (const float*)d_in[8];
    const float* bv = (const float*)d_in[9];
    const float* wo = (const float*)d_in[10];
    const float* bo = (const float*)d_in[11];
    const float* lin1_w = (const float*)d_in[12];
    const float* lin1_b = (const float*)d_in[13];
    const float* lin2_w = (const float*)d_in[14];
    const float* lin2_b = (const float*)d_in[15];
    const float* ln2_w = (const float*)d_in[16];
    const float* ln2_b = (const float*)d_in[17];
    const float* ln3_w = (const float*)d_in[18];
    const float* ln3_b = (const float*)d_in[19];
    const float* learn = (const float*)d_in[20];
    float* out = (float*)d_out;

    k_mask<<<LV, 256>>>(learn);
    k_loss<<<1, 256>>>(out, out_size);
    k_ln1<<<LTOT, 256>>>(src_vid, src_txt, ln1_w, ln1_b);
    k_pos<<<LV, 256>>>(src_vid);

    k_gemm_q<<<dim3(D / 64, LV / 64), 256>>>(wq, bq);
    k_gemm_k<<<dim3(D / 64, LV / 64), 256>>>(wk, bk);
    k_gemm_v<<<dim3(D / 64, LV / 64), 256>>>(wv, bv);

    k_scores<<<dim3(LV / 64, LV / 64, H), 256>>>();
    k_softmax<<<dim3(LV, H), 256>>>();
    k_av<<<dim3(LV / 64, H), 256>>>();

    k_gemm_o<<<dim3(D / 64, LV / 64), 256>>>(wo, bo);
    k_res_ln2<<<LTOT, 256>>>(ln2_w, ln2_b);

    k_gemm_f1<<<dim3(FF / 64, LTOT / 64), 256>>>(lin1_w, lin1_b);
    k_gemm_f2<<<dim3(D / 64, LTOT / 64), 256>>>(lin2_w, lin2_b);

    k_res_ln3<<<LTOT, 256>>>(ln3_w, ln3_b, out);
}

// round 3
// speedup vs baseline: 1.5094x; 1.5094x over previous
#include <cuda_runtime.h>
#include <math.h>

#define LV 2048
#define LT 512
#define LTOT 2560
#define D 512
#define H 8
#define DK 64
#define FF 1024

// ---------------- scratch ----------------
__device__ float g_mask[(size_t)LV * LV];
__device__ float g_partial[LV];
__device__ float g_src[(size_t)LTOT * D];
__device__ float g_src2[(size_t)LTOT * D];
__device__ float g_posq[(size_t)LV * D];
__device__ float g_qin[(size_t)LV * D];
__device__ float g_kin[(size_t)LV * D];
__device__ float g_qh[(size_t)LV * D];
__device__ float g_kh[(size_t)LV * D];
__device__ float g_vh[(size_t)LV * D];
__device__ float g_att[(size_t)LV * D];
__device__ float g_proj[(size_t)LTOT * D];
__device__ float g_ffn[(size_t)LTOT * FF];
__device__ float g_vsuf[(size_t)H * 33 * DK];   // per-head suffix sums of V at 64-row tiles

// ---------------- block reductions (blockDim.x == 256) ----------------
__device__ __forceinline__ float blk_sum(float v, float* sh) {
    int lane = threadIdx.x & 31, wid = threadIdx.x >> 5;
#pragma unroll
    for (int o = 16; o; o >>= 1) v += __shfl_xor_sync(0xffffffffu, v, o);
    if (lane == 0) sh[wid] = v;
    __syncthreads();
    if (threadIdx.x < 32) {
        float t = (threadIdx.x < 8) ? sh[threadIdx.x] : 0.f;
#pragma unroll
        for (int o = 4; o; o >>= 1) t += __shfl_xor_sync(0xffffffffu, t, o);
        if (threadIdx.x == 0) sh[0] = t;
    }
    __syncthreads();
    float r = sh[0];
    __syncthreads();
    return r;
}

// ---------------- mask + sparsity-loss partials ----------------
__global__ void k_mask(const float* __restrict__ learn) {
    int n = blockIdx.x;
    __shared__ float sh[32];
    const float L2G = -0.15200309344504997f; // log2(0.9)
    float psum = 0.f;
    for (int m = threadIdx.x; m < LV; m += 256) {
        float lw = learn[(size_t)n * LV + m];
        float sig = 1.f / (1.f + expf(-lw));
        float maskv;
        if (m == n) {
            maskv = 1.f;
        } else if (n > m) {
            maskv = exp2f((float)(n - m) * L2G) * sig;
            psum += sig;
        } else {
            maskv = 0.f;
            psum += sig;
        }
        g_mask[(size_t)n * LV + m] = maskv;
    }
    float t = blk_sum(psum, sh);
    if (threadIdx.x == 0) g_partial[n] = t;
}

__global__ void k_loss(float* out, int out_size) {
    __shared__ float sh[32];
    float s = 0.f;
    for (int i = threadIdx.x; i < LV; i += 256) s += g_partial[i];
    s = blk_sum(s, sh);
    if (threadIdx.x == 0 && out_size > LV * D + LT * D)
        out[(size_t)LV * D + (size_t)LT * D] = s / ((float)LV * (float)LV);
}

// ---------------- concat + LN1 ----------------
__global__ void k_ln1(const float* __restrict__ vid, const float* __restrict__ txt,
                      const float* __restrict__ w, const float* __restrict__ b) {
    int r = blockIdx.x;
    const float* x = (r < LV) ? (vid + (size_t)r * D) : (txt + (size_t)(r - LV) * D);
    __shared__ float sh[32];
    int i0 = threadIdx.x, i1 = threadIdx.x + 256;
    float v0 = x[i0], v1 = x[i1];
    float s = blk_sum(v0 + v1, sh);
    float s2 = blk_sum(v0 * v0 + v1 * v1, sh);
    float mu = s * (1.f / D);
    float var = s2 * (1.f / D) - mu * mu;
    float inv = rsqrtf(var + 1e-5f);
    size_t o = (size_t)r * D;
    g_src[o + i0] = v0;
    g_src[o + i1] = v1;
    g_src2[o + i0] = (v0 - mu) * inv * w[i0] + b[i0];
    g_src2[o + i1] = (v1 - mu) * inv * w[i1] + b[i1];
}

// ---------------- xpos positional encodings + q/k inputs ----------------
__global__ void k_pos(const float* __restrict__ vid) {
    int r = blockIdx.x;
    int j = threadIdx.x;
    const float L2_1E4 = 13.287712379549449f;
    float sj = (2.f * (float)j + 204.8f) / 716.8f;
    float scale = exp2f(((float)r / 512.f) * log2f(sj));
    float invf = exp2f(-((float)j / 256.f) * L2_1E4);
    float ang = (float)r * invf;
    float sn, cs;
    sincosf(ang, &sn, &cs);
    size_t o = (size_t)r * D + 2 * j;
    float x0 = vid[o], x1 = vid[o + 1];
    float cq = cs * scale, sq = sn * scale;
    float pq0 = x0 * cq - x1 * sq;
    float pq1 = x1 * cq + x0 * sq;
    float iscale = 1.f / scale;
    float ck = cs * iscale, sk = sn * iscale;
    float pk0 = x0 * ck - x1 * sk;
    float pk1 = x1 * ck + x0 * sk;
    g_posq[o] = pq0; g_posq[o + 1] = pq1;
    float n0 = g_src2[o], n1 = g_src2[o + 1];
    g_qin[o] = n0 + pq0; g_qin[o + 1] = n1 + pq1;
    g_kin[o] = n0 + pk0; g_kin[o + 1] = n1 + pk1;
}

// ---------------- SGEMM: C(M x N) = alpha*(A(MxK) @ B(NxK)^T + bias), opt GELU ----------------
// BM=64 (blockIdx.y), BN=128 (blockIdx.x), BK=16, 256 threads, micro 4x8.
__device__ __forceinline__ void gemm_body(const float* __restrict__ A, const float* __restrict__ B,
                                          const float* __restrict__ bias, float* __restrict__ C,
                                          int N, int K, float alpha, int act) {
    __shared__ float As[16][68];
    __shared__ float Bs[16][132];
    int bm = blockIdx.y * 64, bn = blockIdx.x * 128;
    int t = threadIdx.x;
    int ty = t >> 4, tx = t & 15;
    float acc[4][8] = {};
    for (int k0 = 0; k0 < K; k0 += 16) {
        {
            int row = t >> 2, k4 = (t & 3) << 2;
            float4 a = *(const float4*)(A + (size_t)(bm + row) * K + k0 + k4);
            As[k4][row] = a.x; As[k4 + 1][row] = a.y; As[k4 + 2][row] = a.z; As[k4 + 3][row] = a.w;
        }
#pragma unroll
        for (int l = 0; l < 2; l++) {
            int idx = t + l * 256;
            int row = idx >> 2, k4 = (idx & 3) << 2;
            float4 b = *(const float4*)(B + (size_t)(bn + row) * K + k0 + k4);
            Bs[k4][row] = b.x; Bs[k4 + 1][row] = b.y; Bs[k4 + 2][row] = b.z; Bs[k4 + 3][row] = b.w;
        }
        __syncthreads();
#pragma unroll
        for (int kk = 0; kk < 16; kk++) {
            float4 a4 = *(const float4*)&As[kk][ty * 4];
            float4 b4a = *(const float4*)&Bs[kk][tx * 8];
            float4 b4b = *(const float4*)&Bs[kk][tx * 8 + 4];
            float a[4] = {a4.x, a4.y, a4.z, a4.w};
            float b[8] = {b4a.x, b4a.y, b4a.z, b4a.w, b4b.x, b4b.y, b4b.z, b4b.w};
#pragma unroll
            for (int i = 0; i < 4; i++)
#pragma unroll
                for (int j = 0; j < 8; j++)
                    acc[i][j] = fmaf(a[i], b[j], acc[i][j]);
        }
        __syncthreads();
    }
#pragma unroll
    for (int i = 0; i < 4; i++) {
        int row = bm + ty * 4 + i;
        float r[8];
#pragma unroll
        for (int j = 0; j < 8; j++) {
            int col = bn + tx * 8 + j;
            float v = (acc[i][j] + bias[col]) * alpha;
            if (act) v = 0.5f * v * (1.f + erff(v * 0.70710678118654752f));
            r[j] = v;
        }
        float* cp = C + (size_t)row * N + bn + tx * 8;
        *(float4*)cp = make_float4(r[0], r[1], r[2], r[3]);
        *(float4*)(cp + 4) = make_float4(r[4], r[5], r[6], r[7]);
    }
}

// fused QKV (z selects which)
__global__ void k_gemm_qkv(const float* wq, const float* bq, const float* wk, const float* bk,
                           const float* wv, const float* bv) {
    int z = blockIdx.z;
    const float* A = (z == 0) ? g_qin : (z == 1) ? g_kin : g_src2;
    const float* W = (z == 0) ? wq : (z == 1) ? wk : wv;
    const float* B = (z == 0) ? bq : (z == 1) ? bk : bv;
    float* C = (z == 0) ? g_qh : (z == 1) ? g_kh : g_vh;
    float alpha = (z == 0) ? 0.125f : 1.f;
    gemm_body(A, W, B, C, D, D, alpha, 0);
}
__global__ void k_gemm_o(const float* w, const float* b) { gemm_body(g_att, w, b, g_proj, D, D, 1.f, 0); }
__global__ void k_gemm_f1(const float* w, const float* b) { gemm_body(g_src2, w, b, g_ffn, FF, D, 1.f, 1); }
__global__ void k_gemm_f2(const float* w, const float* b) { gemm_body(g_ffn, w, b, g_proj, D, FF, 1.f, 0); }

// ---------------- V suffix sums (per head, 64-row tile granularity) ----------------
__global__ void k_vsuf() {
    int tb = blockIdx.x + 1;   // 1..32
    int h = blockIdx.y;
    int d = threadIdx.x & 63, rg = threadIdx.x >> 6;
    float s = 0.f;
    for (int m = tb * 64 + rg; m < LV; m += 4)
        s += g_vh[(size_t)m * D + h * DK + d];
    __shared__ float sh[4][64];
    sh[rg][d] = s;
    __syncthreads();
    if (rg == 0)
        g_vsuf[((size_t)h * 33 + tb) * DK + d] = sh[0][d] + sh[1][d] + sh[2][d] + sh[3][d];
}

// ---------------- flash attention (causal via mask zeros + analytic tail) ----------------
// grid (32 row tiles, 8 heads), 256 threads. Row tile 64, col tile 64.
__global__ void __launch_bounds__(256) k_flash() {
    __shared__ float Qs[64][64];
    __shared__ float Ks[64][64];   // XOR-swizzled; reused for P tile
    __shared__ float Vs[64][64];
    int h = blockIdx.y;
    int rt = (int)gridDim.x - 1 - (int)blockIdx.x;   // big blocks first
    int bm = rt * 64;
    int ntiles = rt + 1;
    int t = threadIdx.x;
    int ty = t >> 4, tx = t & 15;

    // load Q tile
#pragma unroll
    for (int l = 0; l < 4; l++) {
        int idx = t + l * 256;                 // 0..1023
        int r = idx >> 4, k4 = (idx & 15) << 2;
        float4 q = *(const float4*)(g_qh + (size_t)(bm + r) * D + h * DK + k4);
        *(float4*)&Qs[r][k4] = q;
    }

    float m_run[4], l_run[4], acc[4][4];
#pragma unroll
    for (int i = 0; i < 4; i++) {
        m_run[i] = -1e30f; l_run[i] = 0.f;
#pragma unroll
        for (int j = 0; j < 4; j++) acc[i][j] = 0.f;
    }

    for (int tile = 0; tile < ntiles; tile++) {
        int m0 = tile * 64;
        // load K (swizzled) and V tiles
        __syncthreads();
#pragma unroll
        for (int l = 0; l < 4; l++) {
            int idx = t + l * 256;
            int r = idx >> 4, k4 = (idx & 15) << 2;
            float4 kv = *(const float4*)(g_kh + (size_t)(m0 + r) * D + h * DK + k4);
            int sw = r & 31;
            Ks[r][(k4 + 0) ^ sw] = kv.x;
            Ks[r][(k4 + 1) ^ sw] = kv.y;
            Ks[r][(k4 + 2) ^ sw] = kv.z;
            Ks[r][(k4 + 3) ^ sw] = kv.w;
            float4 vv = *(const float4*)(g_vh + (size_t)(m0 + r) * D + h * DK + k4);
            *(float4*)&Vs[r][k4] = vv;
        }
        __syncthreads();

        // S = Q K^T  (rows ty*4+i, cols tx*4+j)
        float s[4][4] = {};
        int rb[4], sw[4];
#pragma unroll
        for (int j = 0; j < 4; j++) { rb[j] = tx * 4 + j; sw[j] = rb[j] & 31; }
#pragma unroll 16
        for (int kk = 0; kk < 64; kk++) {
            float a[4], b[4];
#pragma unroll
            for (int i = 0; i < 4; i++) a[i] = Qs[ty * 4 + i][kk];
#pragma unroll
            for (int j = 0; j < 4; j++) b[j] = Ks[rb[j]][kk ^ sw[j]];
#pragma unroll
            for (int i = 0; i < 4; i++)
#pragma unroll
                for (int j = 0; j < 4; j++)
                    s[i][j] = fmaf(a[i], b[j], s[i][j]);
        }
        // apply mask (zero above diagonal -> those entries become exact 0 scores)
#pragma unroll
        for (int i = 0; i < 4; i++) {
            float4 mk = *(const float4*)(g_mask + (size_t)(bm + ty * 4 + i) * LV + m0 + tx * 4);
            s[i][0] *= mk.x; s[i][1] *= mk.y; s[i][2] *= mk.z; s[i][3] *= mk.w;
        }
        // online softmax update
        float m_new[4], scale[4], rs[4];
#pragma unroll
        for (int i = 0; i < 4; i++) {
            float tm = fmaxf(fmaxf(s[i][0], s[i][1]), fmaxf(s[i][2], s[i][3]));
#pragma unroll
            for (int o = 8; o; o >>= 1) tm = fmaxf(tm, __shfl_xor_sync(0xffffffffu, tm, o));
            m_new[i] = fmaxf(m_run[i], tm);
            scale[i] = __expf(m_run[i] - m_new[i]);
            float r = 0.f;
#pragma unroll
            for (int j = 0; j < 4; j++) {
                s[i][j] = __expf(s[i][j] - m_new[i]);
                r += s[i][j];
            }
#pragma unroll
            for (int o = 8; o; o >>= 1) r += __shfl_xor_sync(0xffffffffu, r, o);
            rs[i] = r;
        }
#pragma unroll
        for (int i = 0; i < 4; i++) {
            l_run[i] = l_run[i] * scale[i] + rs[i];
            m_run[i] = m_new[i];
#pragma unroll
            for (int j = 0; j < 4; j++) acc[i][j] *= scale[i];
        }
        // write P into Ks buffer (swizzled), then PV
        __syncthreads();
#pragma unroll
        for (int i = 0; i < 4; i++) {
            int r = ty * 4 + i, swr = r & 31;
#pragma unroll
            for (int j = 0; j < 4; j++) Ks[r][(tx * 4 + j) ^ swr] = s[i][j];
        }
        __syncthreads();
#pragma unroll 16
        for (int kk = 0; kk < 64; kk++) {
            float a[4];
#pragma unroll
            for (int i = 0; i < 4; i++) { int r = ty * 4 + i; a[i] = Ks[r][kk ^ (r & 31)]; }
            float4 b4 = *(const float4*)&Vs[kk][tx * 4];
            float b[4] = {b4.x, b4.y, b4.z, b4.w};
#pragma unroll
            for (int i = 0; i < 4; i++)
#pragma unroll
                for (int j = 0; j < 4; j++)
                    acc[i][j] = fmaf(a[i], b[j], acc[i][j]);
        }
    }

    // analytic tail: columns m >= bm+64 all have score exactly 0
    float nz = (float)(LV - (bm + 64));
    int tb = rt + 1;
    float4 sv = *(const float4*)(g_vsuf + ((size_t)h * 33 + tb) * DK + tx * 4);
    float suf[4] = {sv.x, sv.y, sv.z, sv.w};
#pragma unroll
    for (int i = 0; i < 4; i++) {
        float p0 = __expf(-m_run[i]);
        float inv = 1.f / (l_run[i] + nz * p0);
        float* op = g_att + (size_t)(bm + ty * 4 + i) * D + h * DK + tx * 4;
        float4 o4 = make_float4((acc[i][0] + p0 * suf[0]) * inv,
                                (acc[i][1] + p0 * suf[1]) * inv,
                                (acc[i][2] + p0 * suf[2]) * inv,
                                (acc[i][3] + p0 * suf[3]) * inv);
        *(float4*)op = o4;
    }
}

// ---------------- residual + pos + LN2 ----------------
__device__ __forceinline__ float sine_pos_elem(float xe, int i) {
    const float L2_1E4 = 13.287712379549449f;
    int j = i >> 1;
    float dim = exp2f(((float)j / 256.f) * L2_1E4);
    float val = xe / dim;
    return (i & 1) ? cosf(val) : sinf(val);
}

__global__ void k_res_ln2(const float* __restrict__ w, const float* __restrict__ b) {
    int r = blockIdx.x;
    __shared__ float sh[32];
    int i0 = threadIdx.x, i1 = threadIdx.x + 256;
    size_t o = (size_t)r * D;
    float v0, v1;
    if (r < LV) {
        v0 = g_src[o + i0] + g_proj[o + i0] + g_posq[o + i0];
        v1 = g_src[o + i1] + g_proj[o + i1] + g_posq[o + i1];
    } else {
        int tt = r - LV;
        float xe = (float)(tt + 1) / (512.f + 1e-6f) * 6.283185307179586f;
        v0 = g_src[o + i0] + g_src2[o + i0] + sine_pos_elem(xe, i0);
        v1 = g_src[o + i1] + g_src2[o + i1] + sine_pos_elem(xe, i1);
    }
    float s = blk_sum(v0 + v1, sh);
    float s2 = blk_sum(v0 * v0 + v1 * v1, sh);
    float mu = s * (1.f / D);
    float var = s2 * (1.f / D) - mu * mu;
    float inv = rsqrtf(var + 1e-5f);
    g_src[o + i0] = v0;
    g_src[o + i1] = v1;
    g_src2[o + i0] = (v0 - mu) * inv * w[i0] + b[i0];
    g_src2[o + i1] = (v1 - mu) * inv * w[i1] + b[i1];
}

// ---------------- residual + LN3 + output ----------------
__global__ void k_res_ln3(const float* __restrict__ w, const float* __restrict__ b,
                          float* __restrict__ out) {
    int r = blockIdx.x;
    __shared__ float sh[32];
    int i0 = threadIdx.x, i1 = threadIdx.x + 256;
    size_t o = (size_t)r * D;
    float v0 = g_src[o + i0] + g_proj[o + i0];
    float v1 = g_src[o + i1] + g_proj[o + i1];
    float s = blk_sum(v0 + v1, sh);
    float s2 = blk_sum(v0 * v0 + v1 * v1, sh);
    float mu = s * (1.f / D);
    float var = s2 * (1.f / D) - mu * mu;
    float inv = rsqrtf(var + 1e-5f);
    out[o + i0] = (v0 - mu) * inv * w[i0] + b[i0];
    out[o + i1] = (v1 - mu) * inv * w[i1] + b[i1];
}

extern "C" void kernel_launch(void* const* d_in, const int* in_sizes, int n_in,
                              void* d_out, int out_size) {
    const float* src_vid = (const float*)d_in[0];
    const float* src_txt = (const float*)d_in[1];
    const float* ln1_w = (const float*)d_in[2];
    const float* ln1_b = (const float*)d_in[3];
    const float* wq = (const float*)d_in[4];
    const float* bq = (const float*)d_in[5];
    const float* wk = (const float*)d_in[6];
    const float* bk = (const float*)d_in[7];
    const float* wv = (const float*)d_in[8];
    const float* bv = (const float*)d_in[9];
    const float* wo = (const float*)d_in[10];
    const float* bo = (const float*)d_in[11];
    const float* lin1_w = (const float*)d_in[12];
    const float* lin1_b = (const float*)d_in[13];
    const float* lin2_w = (const float*)d_in[14];
    const float* lin2_b = (const float*)d_in[15];
    const float* ln2_w = (const float*)d_in[16];
    const float* ln2_b = (const float*)d_in[17];
    const float* ln3_w = (const float*)d_in[18];
    const float* ln3_b = (const float*)d_in[19];
    const float* learn = (const float*)d_in[20];
    float* out = (float*)d_out;

    k_mask<<<LV, 256>>>(learn);
    k_loss<<<1, 256>>>(out, out_size);
    k_ln1<<<LTOT, 256>>>(src_vid, src_txt, ln1_w, ln1_b);
    k_pos<<<LV, 256>>>(src_vid);

    k_gemm_qkv<<<dim3(D / 128, LV / 64, 3), 256>>>(wq, bq, wk, bk, wv, bv);

    k_vsuf<<<dim3(32, H), 256>>>();
    k_flash<<<dim3(LV / 64, H), 256>>>();

    k_gemm_o<<<dim3(D / 128, LV / 64), 256>>>(wo, bo);
    k_res_ln2<<<LTOT, 256>>>(ln2_w, ln2_b);

    k_gemm_f1<<<dim3(FF / 128, LTOT / 64), 256>>>(lin1_w, lin1_b);
    k_gemm_f2<<<dim3(D / 128, LTOT / 64), 256>>>(lin2_w, lin2_b);

    k_res_ln3<<<LTOT, 256>>>(ln3_w, ln3_b, out);
}

// round 5
// speedup vs baseline: 1.7630x; 1.1680x over previous
#include <cuda_runtime.h>
#include <math.h>
#include <stdint.h>

#define LV 2048
#define LT 512
#define LTOT 2560
#define D 512
#define H 8
#define DK 64
#define FF 1024

// ---------------- scratch ----------------
__device__ float g_mask[(size_t)LV * LV];
__device__ float g_partial[LV];
__device__ float g_src[(size_t)LTOT * D];
__device__ float g_src2[(size_t)LTOT * D];
__device__ float g_posq[(size_t)LV * D];
__device__ float g_qin[(size_t)LV * D];
__device__ float g_kin[(size_t)LV * D];
__device__ float g_qh[(size_t)LV * D];
__device__ float g_kh[(size_t)LV * D];
__device__ float g_vh[(size_t)LV * D];
__device__ float g_att[(size_t)LV * D];
__device__ float g_proj[(size_t)LTOT * D];
__device__ float g_ffn[(size_t)LTOT * FF];
__device__ float g_vsuf[(size_t)H * 33 * DK];

// ---------------- block reductions (blockDim.x == 256) ----------------
__device__ __forceinline__ float blk_sum(float v, float* sh) {
    int lane = threadIdx.x & 31, wid = threadIdx.x >> 5;
#pragma unroll
    for (int o = 16; o; o >>= 1) v += __shfl_xor_sync(0xffffffffu, v, o);
    if (lane == 0) sh[wid] = v;
    __syncthreads();
    if (threadIdx.x < 32) {
        float t = (threadIdx.x < 8) ? sh[threadIdx.x] : 0.f;
#pragma unroll
        for (int o = 4; o; o >>= 1) t += __shfl_xor_sync(0xffffffffu, t, o);
        if (threadIdx.x == 0) sh[0] = t;
    }
    __syncthreads();
    float r = sh[0];
    __syncthreads();
    return r;
}

// ---------------- mask + sparsity-loss partials ----------------
__global__ void k_mask(const float* __restrict__ learn) {
    int n = blockIdx.x;
    __shared__ float sh[32];
    const float L2G = -0.15200309344504997f;
    float psum = 0.f;
    for (int m = threadIdx.x; m < LV; m += 256) {
        float lw = learn[(size_t)n * LV + m];
        float sig = 1.f / (1.f + expf(-lw));
        float maskv;
        if (m == n) {
            maskv = 1.f;
        } else if (n > m) {
            maskv = exp2f((float)(n - m) * L2G) * sig;
            psum += sig;
        } else {
            maskv = 0.f;
            psum += sig;
        }
        g_mask[(size_t)n * LV + m] = maskv;
    }
    float t = blk_sum(psum, sh);
    if (threadIdx.x == 0) g_partial[n] = t;
}

__global__ void k_loss(float* out, int out_size) {
    __shared__ float sh[32];
    float s = 0.f;
    for (int i = threadIdx.x; i < LV; i += 256) s += g_partial[i];
    s = blk_sum(s, sh);
    if (threadIdx.x == 0 && out_size > LV * D + LT * D)
        out[(size_t)LV * D + (size_t)LT * D] = s / ((float)LV * (float)LV);
}

// ---------------- concat + LN1 ----------------
__global__ void k_ln1(const float* __restrict__ vid, const float* __restrict__ txt,
                      const float* __restrict__ w, const float* __restrict__ b) {
    int r = blockIdx.x;
    const float* x = (r < LV) ? (vid + (size_t)r * D) : (txt + (size_t)(r - LV) * D);
    __shared__ float sh[32];
    int i0 = threadIdx.x, i1 = threadIdx.x + 256;
    float v0 = x[i0], v1 = x[i1];
    float s = blk_sum(v0 + v1, sh);
    float s2 = blk_sum(v0 * v0 + v1 * v1, sh);
    float mu = s * (1.f / D);
    float var = s2 * (1.f / D) - mu * mu;
    float inv = rsqrtf(var + 1e-5f);
    size_t o = (size_t)r * D;
    g_src[o + i0] = v0;
    g_src[o + i1] = v1;
    g_src2[o + i0] = (v0 - mu) * inv * w[i0] + b[i0];
    g_src2[o + i1] = (v1 - mu) * inv * w[i1] + b[i1];
}

// ---------------- xpos positional encodings + q/k inputs ----------------
__global__ void k_pos(const float* __restrict__ vid) {
    int r = blockIdx.x;
    int j = threadIdx.x;
    const float L2_1E4 = 13.287712379549449f;
    float sj = (2.f * (float)j + 204.8f) / 716.8f;
    float scale = exp2f(((float)r / 512.f) * log2f(sj));
    float invf = exp2f(-((float)j / 256.f) * L2_1E4);
    float ang = (float)r * invf;
    float sn, cs;
    sincosf(ang, &sn, &cs);
    size_t o = (size_t)r * D + 2 * j;
    float x0 = vid[o], x1 = vid[o + 1];
    float cq = cs * scale, sq = sn * scale;
    float pq0 = x0 * cq - x1 * sq;
    float pq1 = x1 * cq + x0 * sq;
    float iscale = 1.f / scale;
    float ck = cs * iscale, sk = sn * iscale;
    float pk0 = x0 * ck - x1 * sk;
    float pk1 = x1 * ck + x0 * sk;
    g_posq[o] = pq0; g_posq[o + 1] = pq1;
    float n0 = g_src2[o], n1 = g_src2[o + 1];
    g_qin[o] = n0 + pq0; g_qin[o + 1] = n1 + pq1;
    g_kin[o] = n0 + pk0; g_kin[o + 1] = n1 + pk1;
}

// ---------------- tensor-core GEMM (3xTF32 split) ----------------
// C(MxN) = alpha*(A(MxK) @ W(NxK)^T + bias), optional exact GELU.
// Block tile 128x64, BK=16, 256 threads = 8 warps (4M x 2N), warp tile 32x32.
__device__ __forceinline__ uint32_t f2tf(float x) {
    uint32_t r;
    asm("cvt.rna.tf32.f32 %0, %1;" : "=r"(r) : "f"(x));
    return r;
}

__device__ __forceinline__ void mma_tf32(float* d, uint32_t a0, uint32_t a1, uint32_t a2,
                                         uint32_t a3, uint32_t b0, uint32_t b1) {
    asm volatile(
        "mma.sync.aligned.m16n8k8.row.col.f32.tf32.tf32.f32 "
        "{%0,%1,%2,%3}, {%4,%5,%6,%7}, {%8,%9}, {%0,%1,%2,%3};"
        : "+f"(d[0]), "+f"(d[1]), "+f"(d[2]), "+f"(d[3])
        : "r"(a0), "r"(a1), "r"(a2), "r"(a3), "r"(b0), "r"(b1));
}

__device__ __forceinline__ float2 split_tf32(float x) {
    float hi = __uint_as_float(f2tf(x));
    float lo = __uint_as_float(f2tf(x - hi));
    return make_float2(hi, lo);
}

__device__ __forceinline__ void gemm_tc(const float* __restrict__ A, const float* __restrict__ W,
                                        const float* __restrict__ bias, float* __restrict__ C,
                                        int N, int K, float alpha, int act) {
    __shared__ float2 As[128][20];   // (hi, lo) pairs
    __shared__ float2 Bs[64][20];
    int bm = blockIdx.y * 128, bn = blockIdx.x * 64;
    int t = threadIdx.x, warp = t >> 5, lane = t & 31;
    int gid = lane >> 2, tidg = lane & 3;
    int wm = (warp >> 1) * 32, wn = (warp & 1) * 32;

    float d[2][4][4];
#pragma unroll
    for (int mt = 0; mt < 2; mt++)
#pragma unroll
        for (int nt = 0; nt < 4; nt++)
#pragma unroll
            for (int r = 0; r < 4; r++) d[mt][nt][r] = 0.f;

    for (int k0 = 0; k0 < K; k0 += 16) {
#pragma unroll
        for (int l = 0; l < 2; l++) {
            int idx = t + l * 256;
            int row = idx >> 2, c4 = (idx & 3) << 2;
            float4 a = *(const float4*)(A + (size_t)(bm + row) * K + k0 + c4);
            As[row][c4 + 0] = split_tf32(a.x);
            As[row][c4 + 1] = split_tf32(a.y);
            As[row][c4 + 2] = split_tf32(a.z);
            As[row][c4 + 3] = split_tf32(a.w);
        }
        {
            int row = t >> 2, c4 = (t & 3) << 2;
            float4 b = *(const float4*)(W + (size_t)(bn + row) * K + k0 + c4);
            Bs[row][c4 + 0] = split_tf32(b.x);
            Bs[row][c4 + 1] = split_tf32(b.y);
            Bs[row][c4 + 2] = split_tf32(b.z);
            Bs[row][c4 + 3] = split_tf32(b.w);
        }
        __syncthreads();

#pragma unroll
        for (int ks = 0; ks < 2; ks++) {
            int kc = ks * 8;
            float2 af[2][4];
#pragma unroll
            for (int mt = 0; mt < 2; mt++) {
                int r0 = wm + mt * 16 + gid;
                af[mt][0] = As[r0][kc + tidg];
                af[mt][1] = As[r0 + 8][kc + tidg];
                af[mt][2] = As[r0][kc + tidg + 4];
                af[mt][3] = As[r0 + 8][kc + tidg + 4];
            }
            float2 bf[4][2];
#pragma unroll
            for (int nt = 0; nt < 4; nt++) {
                int r0 = wn + nt * 8 + gid;
                bf[nt][0] = Bs[r0][kc + tidg];
                bf[nt][1] = Bs[r0][kc + tidg + 4];
            }
#pragma unroll
            for (int mt = 0; mt < 2; mt++) {
                uint32_t ah[4], al[4];
#pragma unroll
                for (int r = 0; r < 4; r++) {
                    ah[r] = __float_as_uint(af[mt][r].x);
                    al[r] = __float_as_uint(af[mt][r].y);
                }
#pragma unroll
                for (int nt = 0; nt < 4; nt++) {
                    uint32_t bh0 = __float_as_uint(bf[nt][0].x);
                    uint32_t bh1 = __float_as_uint(bf[nt][1].x);
                    uint32_t bl0 = __float_as_uint(bf[nt][0].y);
                    uint32_t bl1 = __float_as_uint(bf[nt][1].y);
                    mma_tf32(d[mt][nt], ah[0], ah[1], ah[2], ah[3], bh0, bh1);
                    mma_tf32(d[mt][nt], ah[0], ah[1], ah[2], ah[3], bl0, bl1);
                    mma_tf32(d[mt][nt], al[0], al[1], al[2], al[3], bh0, bh1);
                }
            }
        }
        __syncthreads();
    }

    // epilogue
#pragma unroll
    for (int mt = 0; mt < 2; mt++) {
        int r0 = bm + wm + mt * 16 + gid;
#pragma unroll
        for (int nt = 0; nt < 4; nt++) {
            int c0 = bn + wn + nt * 8 + 2 * tidg;
            float bia0 = bias[c0], bia1 = bias[c0 + 1];
#pragma unroll
            for (int half = 0; half < 2; half++) {
                int row = r0 + half * 8;
                float v0 = (d[mt][nt][half * 2 + 0] + bia0) * alpha;
                float v1 = (d[mt][nt][half * 2 + 1] + bia1) * alpha;
                if (act) {
                    v0 = 0.5f * v0 * (1.f + erff(v0 * 0.70710678118654752f));
                    v1 = 0.5f * v1 * (1.f + erff(v1 * 0.70710678118654752f));
                }
                C[(size_t)row * N + c0] = v0;
                C[(size_t)row * N + c0 + 1] = v1;
            }
        }
    }
}

__global__ void __launch_bounds__(256) k_gemm_qkv(const float* wq, const float* bq,
                                                  const float* wk, const float* bk,
                                                  const float* wv, const float* bv) {
    int z = blockIdx.z;
    const float* A = (z == 0) ? g_qin : (z == 1) ? g_kin : g_src2;
    const float* W = (z == 0) ? wq : (z == 1) ? wk : wv;
    const float* B = (z == 0) ? bq : (z == 1) ? bk : bv;
    float* C = (z == 0) ? g_qh : (z == 1) ? g_kh : g_vh;
    float alpha = (z == 0) ? 0.125f : 1.f;
    gemm_tc(A, W, B, C, D, D, alpha, 0);
}
__global__ void __launch_bounds__(256) k_gemm_o(const float* w, const float* b) {
    gemm_tc(g_att, w, b, g_proj, D, D, 1.f, 0);
}
__global__ void __launch_bounds__(256) k_gemm_f1(const float* w, const float* b) {
    gemm_tc(g_src2, w, b, g_ffn, FF, D, 1.f, 1);
}
__global__ void __launch_bounds__(256) k_gemm_f2(const float* w, const float* b) {
    gemm_tc(g_ffn, w, b, g_proj, D, FF, 1.f, 0);
}

// ---------------- V suffix sums ----------------
__global__ void k_vsuf() {
    int tb = blockIdx.x + 1;
    int h = blockIdx.y;
    int d = threadIdx.x & 63, rg = threadIdx.x >> 6;
    float s = 0.f;
    for (int m = tb * 64 + rg; m < LV; m += 4)
        s += g_vh[(size_t)m * D + h * DK + d];
    __shared__ float sh[4][64];
    sh[rg][d] = s;
    __syncthreads();
    if (rg == 0)
        g_vsuf[((size_t)h * 33 + tb) * DK + d] = sh[0][d] + sh[1][d] + sh[2][d] + sh[3][d];
}

// ---------------- flash attention (causal + analytic tail) ----------------
__global__ void __launch_bounds__(256) k_flash() {
    __shared__ float Qs[64][64];
    __shared__ float Ks[64][64];
    __shared__ float Vs[64][64];
    int h = blockIdx.y;
    int rt = (int)gridDim.x - 1 - (int)blockIdx.x;
    int bm = rt * 64;
    int ntiles = rt + 1;
    int t = threadIdx.x;
    int ty = t >> 4, tx = t & 15;

#pragma unroll
    for (int l = 0; l < 4; l++) {
        int idx = t + l * 256;
        int r = idx >> 4, k4 = (idx & 15) << 2;
        float4 q = *(const float4*)(g_qh + (size_t)(bm + r) * D + h * DK + k4);
        *(float4*)&Qs[r][k4] = q;
    }

    float m_run[4], l_run[4], acc[4][4];
#pragma unroll
    for (int i = 0; i < 4; i++) {
        m_run[i] = -1e30f; l_run[i] = 0.f;
#pragma unroll
        for (int j = 0; j < 4; j++) acc[i][j] = 0.f;
    }

    for (int tile = 0; tile < ntiles; tile++) {
        int m0 = tile * 64;
        __syncthreads();
#pragma unroll
        for (int l = 0; l < 4; l++) {
            int idx = t + l * 256;
            int r = idx >> 4, k4 = (idx & 15) << 2;
            float4 kv = *(const float4*)(g_kh + (size_t)(m0 + r) * D + h * DK + k4);
            int sw = r & 31;
            Ks[r][(k4 + 0) ^ sw] = kv.x;
            Ks[r][(k4 + 1) ^ sw] = kv.y;
            Ks[r][(k4 + 2) ^ sw] = kv.z;
            Ks[r][(k4 + 3) ^ sw] = kv.w;
            float4 vv = *(const float4*)(g_vh + (size_t)(m0 + r) * D + h * DK + k4);
            *(float4*)&Vs[r][k4] = vv;
        }
        __syncthreads();

        float s[4][4] = {};
        int rb[4], sw[4];
#pragma unroll
        for (int j = 0; j < 4; j++) { rb[j] = tx * 4 + j; sw[j] = rb[j] & 31; }
#pragma unroll 16
        for (int kk = 0; kk < 64; kk++) {
            float a[4], b[4];
#pragma unroll
            for (int i = 0; i < 4; i++) a[i] = Qs[ty * 4 + i][kk];
#pragma unroll
            for (int j = 0; j < 4; j++) b[j] = Ks[rb[j]][kk ^ sw[j]];
#pragma unroll
            for (int i = 0; i < 4; i++)
#pragma unroll
                for (int j = 0; j < 4; j++)
                    s[i][j] = fmaf(a[i], b[j], s[i][j]);
        }
#pragma unroll
        for (int i = 0; i < 4; i++) {
            float4 mk = *(const float4*)(g_mask + (size_t)(bm + ty * 4 + i) * LV + m0 + tx * 4);
            s[i][0] *= mk.x; s[i][1] *= mk.y; s[i][2] *= mk.z; s[i][3] *= mk.w;
        }
        float m_new[4], scale[4], rs[4];
#pragma unroll
        for (int i = 0; i < 4; i++) {
            float tm = fmaxf(fmaxf(s[i][0], s[i][1]), fmaxf(s[i][2], s[i][3]));
#pragma unroll
            for (int o = 8; o; o >>= 1) tm = fmaxf(tm, __shfl_xor_sync(0xffffffffu, tm, o));
            m_new[i] = fmaxf(m_run[i], tm);
            scale[i] = __expf(m_run[i] - m_new[i]);
            float r = 0.f;
#pragma unroll
            for (int j = 0; j < 4; j++) {
                s[i][j] = __expf(s[i][j] - m_new[i]);
                r += s[i][j];
            }
#pragma unroll
            for (int o = 8; o; o >>= 1) r += __shfl_xor_sync(0xffffffffu, r, o);
            rs[i] = r;
        }
#pragma unroll
        for (int i = 0; i < 4; i++) {
            l_run[i] = l_run[i] * scale[i] + rs[i];
            m_run[i] = m_new[i];
#pragma unroll
            for (int j = 0; j < 4; j++) acc[i][j] *= scale[i];
        }
        __syncthreads();
#pragma unroll
        for (int i = 0; i < 4; i++) {
            int r = ty * 4 + i, swr = r & 31;
#pragma unroll
            for (int j = 0; j < 4; j++) Ks[r][(tx * 4 + j) ^ swr] = s[i][j];
        }
        __syncthreads();
#pragma unroll 16
        for (int kk = 0; kk < 64; kk++) {
            float a[4];
#pragma unroll
            for (int i = 0; i < 4; i++) { int r = ty * 4 + i; a[i] = Ks[r][kk ^ (r & 31)]; }
            float4 b4 = *(const float4*)&Vs[kk][tx * 4];
            float b[4] = {b4.x, b4.y, b4.z, b4.w};
#pragma unroll
            for (int i = 0; i < 4; i++)
#pragma unroll
                for (int j = 0; j < 4; j++)
                    acc[i][j] = fmaf(a[i], b[j], acc[i][j]);
        }
    }

    float nz = (float)(LV - (bm + 64));
    int tb = rt + 1;
    float4 sv = *(const float4*)(g_vsuf + ((size_t)h * 33 + tb) * DK + tx * 4);
    float suf[4] = {sv.x, sv.y, sv.z, sv.w};
#pragma unroll
    for (int i = 0; i < 4; i++) {
        float p0 = __expf(-m_run[i]);
        float inv = 1.f / (l_run[i] + nz * p0);
        float* op = g_att + (size_t)(bm + ty * 4 + i) * D + h * DK + tx * 4;
        float4 o4 = make_float4((acc[i][0] + p0 * suf[0]) * inv,
                                (acc[i][1] + p0 * suf[1]) * inv,
                                (acc[i][2] + p0 * suf[2]) * inv,
                                (acc[i][3] + p0 * suf[3]) * inv);
        *(float4*)op = o4;
    }
}

// ---------------- residual + pos + LN2 ----------------
__device__ __forceinline__ float sine_pos_elem(float xe, int i) {
    const float L2_1E4 = 13.287712379549449f;
    int j = i >> 1;
    float dim = exp2f(((float)j / 256.f) * L2_1E4);
    float val = xe / dim;
    return (i & 1) ? cosf(val) : sinf(val);
}

__global__ void k_res_ln2(const float* __restrict__ w, const float* __restrict__ b) {
    int r = blockIdx.x;
    __shared__ float sh[32];
    int i0 = threadIdx.x, i1 = threadIdx.x + 256;
    size_t o = (size_t)r * D;
    float v0, v1;
    if (r < LV) {
        v0 = g_src[o + i0] + g_proj[o + i0] + g_posq[o + i0];
        v1 = g_src[o + i1] + g_proj[o + i1] + g_posq[o + i1];
    } else {
        int tt = r - LV;
        float xe = (float)(tt + 1) / (512.f + 1e-6f) * 6.283185307179586f;
        v0 = g_src[o + i0] + g_src2[o + i0] + sine_pos_elem(xe, i0);
        v1 = g_src[o + i1] + g_src2[o + i1] + sine_pos_elem(xe, i1);
    }
    float s = blk_sum(v0 + v1, sh);
    float s2 = blk_sum(v0 * v0 + v1 * v1, sh);
    float mu = s * (1.f / D);
    float var = s2 * (1.f / D) - mu * mu;
    float inv = rsqrtf(var + 1e-5f);
    g_src[o + i0] = v0;
    g_src[o + i1] = v1;
    g_src2[o + i0] = (v0 - mu) * inv * w[i0] + b[i0];
    g_src2[o + i1] = (v1 - mu) * inv * w[i1] + b[i1];
}

// ---------------- residual + LN3 + output ----------------
__global__ void k_res_ln3(const float* __restrict__ w, const float* __restrict__ b,
                          float* __restrict__ out) {
    int r = blockIdx.x;
    __shared__ float sh[32];
    int i0 = threadIdx.x, i1 = threadIdx.x + 256;
    size_t o = (size_t)r * D;
    float v0 = g_src[o + i0] + g_proj[o + i0];
    float v1 = g_src[o + i1] + g_proj[o + i1];
    float s = blk_sum(v0 + v1, sh);
    float s2 = blk_sum(v0 * v0 + v1 * v1, sh);
    float mu = s * (1.f / D);
    float var = s2 * (1.f / D) - mu * mu;
    float inv = rsqrtf(var + 1e-5f);
    out[o + i0] = (v0 - mu) * inv * w[i0] + b[i0];
    out[o + i1] = (v1 - mu) * inv * w[i1] + b[i1];
}

extern "C" void kernel_launch(void* const* d_in, const int* in_sizes, int n_in,
                              void* d_out, int out_size) {
    const float* src_vid = (const float*)d_in[0];
    const float* src_txt = (const float*)d_in[1];
    const float* ln1_w = (const float*)d_in[2];
    const float* ln1_b = (const float*)d_in[3];
    const float* wq = (const float*)d_in[4];
    const float* bq = (const float*)d_in[5];
    const float* wk = (const float*)d_in[6];
    const float* bk = (const float*)d_in[7];
    const float* wv = (const float*)d_in[8];
    const float* bv = (const float*)d_in[9];
    const float* wo = (const float*)d_in[10];
    const float* bo = (const float*)d_in[11];
    const float* lin1_w = (const float*)d_in[12];
    const float* lin1_b = (const float*)d_in[13];
    const float* lin2_w = (const float*)d_in[14];
    const float* lin2_b = (const float*)d_in[15];
    const float* ln2_w = (const float*)d_in[16];
    const float* ln2_b = (const float*)d_in[17];
    const float* ln3_w = (const float*)d_in[18];
    const float* ln3_b = (const float*)d_in[19];
    const float* learn = (const float*)d_in[20];
    float* out = (float*)d_out;

    k_mask<<<LV, 256>>>(learn);
    k_loss<<<1, 256>>>(out, out_size);
    k_ln1<<<LTOT, 256>>>(src_vid, src_txt, ln1_w, ln1_b);
    k_pos<<<LV, 256>>>(src_vid);

    k_gemm_qkv<<<dim3(D / 64, LV / 128, 3), 256>>>(wq, bq, wk, bk, wv, bv);

    k_vsuf<<<dim3(32, H), 256>>>();
    k_flash<<<dim3(LV / 64, H), 256>>>();

    k_gemm_o<<<dim3(D / 64, LV / 128), 256>>>(wo, bo);
    k_res_ln2<<<LTOT, 256>>>(ln2_w, ln2_b);

    k_gemm_f1<<<dim3(FF / 64, LTOT / 128), 256>>>(lin1_w, lin1_b);
    k_gemm_f2<<<dim3(D / 64, LTOT / 128), 256>>>(lin2_w, lin2_b);

    k_res_ln3<<<LTOT, 256>>>(ln3_w, ln3_b, out);
}

// round 6
// speedup vs baseline: 2.1139x; 1.1990x over previous
#include <cuda_runtime.h>
#include <math.h>
#include <stdint.h>

#define LV 2048
#define LT 512
#define LTOT 2560
#define D 512
#define H 8
#define DK 64
#define FF 1024

// ---------------- scratch ----------------
__device__ float g_mask[(size_t)LV * LV];
__device__ float g_partial[LV];
__device__ float g_src[(size_t)LTOT * D];
__device__ float g_src2[(size_t)LTOT * D];
__device__ float g_posq[(size_t)LV * D];
__device__ float g_qin[(size_t)LV * D];
__device__ float g_kin[(size_t)LV * D];
__device__ float g_qh[(size_t)LV * D];
__device__ float g_kh[(size_t)LV * D];
__device__ float g_vh[(size_t)LV * D];
__device__ float g_att[(size_t)LV * D];
__device__ float g_proj[(size_t)LTOT * D];
__device__ float g_ffn[(size_t)LTOT * FF];
__device__ float g_vsuf[(size_t)H * 33 * DK];

// ---------------- block reductions (blockDim.x == 256) ----------------
__device__ __forceinline__ float blk_sum(float v, float* sh) {
    int lane = threadIdx.x & 31, wid = threadIdx.x >> 5;
#pragma unroll
    for (int o = 16; o; o >>= 1) v += __shfl_xor_sync(0xffffffffu, v, o);
    if (lane == 0) sh[wid] = v;
    __syncthreads();
    if (threadIdx.x < 32) {
        float t = (threadIdx.x < 8) ? sh[threadIdx.x] : 0.f;
#pragma unroll
        for (int o = 4; o; o >>= 1) t += __shfl_xor_sync(0xffffffffu, t, o);
        if (threadIdx.x == 0) sh[0] = t;
    }
    __syncthreads();
    float r = sh[0];
    __syncthreads();
    return r;
}

// ---------------- mask + sparsity-loss partials ----------------
__global__ void k_mask(const float* __restrict__ learn) {
    int n = blockIdx.x;
    __shared__ float sh[32];
    const float L2G = -0.15200309344504997f;
    float psum = 0.f;
    for (int m = threadIdx.x; m < LV; m += 256) {
        float lw = learn[(size_t)n * LV + m];
        float sig = 1.f / (1.f + expf(-lw));
        float maskv;
        if (m == n) {
            maskv = 1.f;
        } else if (n > m) {
            maskv = exp2f((float)(n - m) * L2G) * sig;
            psum += sig;
        } else {
            maskv = 0.f;
            psum += sig;
        }
        g_mask[(size_t)n * LV + m] = maskv;
    }
    float t = blk_sum(psum, sh);
    if (threadIdx.x == 0) g_partial[n] = t;
}

__global__ void k_loss(float* out, int out_size) {
    __shared__ float sh[32];
    float s = 0.f;
    for (int i = threadIdx.x; i < LV; i += 256) s += g_partial[i];
    s = blk_sum(s, sh);
    if (threadIdx.x == 0 && out_size > LV * D + LT * D)
        out[(size_t)LV * D + (size_t)LT * D] = s / ((float)LV * (float)LV);
}

// ---------------- concat + LN1 ----------------
__global__ void k_ln1(const float* __restrict__ vid, const float* __restrict__ txt,
                      const float* __restrict__ w, const float* __restrict__ b) {
    int r = blockIdx.x;
    const float* x = (r < LV) ? (vid + (size_t)r * D) : (txt + (size_t)(r - LV) * D);
    __shared__ float sh[32];
    int i0 = threadIdx.x, i1 = threadIdx.x + 256;
    float v0 = x[i0], v1 = x[i1];
    float s = blk_sum(v0 + v1, sh);
    float s2 = blk_sum(v0 * v0 + v1 * v1, sh);
    float mu = s * (1.f / D);
    float var = s2 * (1.f / D) - mu * mu;
    float inv = rsqrtf(var + 1e-5f);
    size_t o = (size_t)r * D;
    g_src[o + i0] = v0;
    g_src[o + i1] = v1;
    g_src2[o + i0] = (v0 - mu) * inv * w[i0] + b[i0];
    g_src2[o + i1] = (v1 - mu) * inv * w[i1] + b[i1];
}

// ---------------- xpos positional encodings + q/k inputs ----------------
__global__ void k_pos(const float* __restrict__ vid) {
    int r = blockIdx.x;
    int j = threadIdx.x;
    const float L2_1E4 = 13.287712379549449f;
    float sj = (2.f * (float)j + 204.8f) / 716.8f;
    float scale = exp2f(((float)r / 512.f) * log2f(sj));
    float invf = exp2f(-((float)j / 256.f) * L2_1E4);
    float ang = (float)r * invf;
    float sn, cs;
    sincosf(ang, &sn, &cs);
    size_t o = (size_t)r * D + 2 * j;
    float x0 = vid[o], x1 = vid[o + 1];
    float cq = cs * scale, sq = sn * scale;
    float pq0 = x0 * cq - x1 * sq;
    float pq1 = x1 * cq + x0 * sq;
    float iscale = 1.f / scale;
    float ck = cs * iscale, sk = sn * iscale;
    float pk0 = x0 * ck - x1 * sk;
    float pk1 = x1 * ck + x0 * sk;
    g_posq[o] = pq0; g_posq[o + 1] = pq1;
    float n0 = g_src2[o], n1 = g_src2[o + 1];
    g_qin[o] = n0 + pq0; g_qin[o + 1] = n1 + pq1;
    g_kin[o] = n0 + pk0; g_kin[o + 1] = n1 + pk1;
}

// ---------------- TF32 helpers ----------------
__device__ __forceinline__ uint32_t f2tf(float x) {
    uint32_t r;
    asm("cvt.rna.tf32.f32 %0, %1;" : "=r"(r) : "f"(x));
    return r;
}

__device__ __forceinline__ void mma_tf32(float* d, uint32_t a0, uint32_t a1, uint32_t a2,
                                         uint32_t a3, uint32_t b0, uint32_t b1) {
    asm volatile(
        "mma.sync.aligned.m16n8k8.row.col.f32.tf32.tf32.f32 "
        "{%0,%1,%2,%3}, {%4,%5,%6,%7}, {%8,%9}, {%0,%1,%2,%3};"
        : "+f"(d[0]), "+f"(d[1]), "+f"(d[2]), "+f"(d[3])
        : "r"(a0), "r"(a1), "r"(a2), "r"(a3), "r"(b0), "r"(b1));
}

__device__ __forceinline__ float2 split_tf32(float x) {
    float hi = __uint_as_float(f2tf(x));
    float lo = __uint_as_float(f2tf(x - hi));
    return make_float2(hi, lo);
}

// ---------------- tensor-core GEMM (3xTF32 split) ----------------
__device__ __forceinline__ void gemm_tc(const float* __restrict__ A, const float* __restrict__ W,
                                        const float* __restrict__ bias, float* __restrict__ C,
                                        int N, int K, float alpha, int act) {
    __shared__ float2 As[128][20];
    __shared__ float2 Bs[64][20];
    int bm = blockIdx.y * 128, bn = blockIdx.x * 64;
    int t = threadIdx.x, warp = t >> 5, lane = t & 31;
    int gid = lane >> 2, tidg = lane & 3;
    int wm = (warp >> 1) * 32, wn = (warp & 1) * 32;

    float d[2][4][4];
#pragma unroll
    for (int mt = 0; mt < 2; mt++)
#pragma unroll
        for (int nt = 0; nt < 4; nt++)
#pragma unroll
            for (int r = 0; r < 4; r++) d[mt][nt][r] = 0.f;

    for (int k0 = 0; k0 < K; k0 += 16) {
#pragma unroll
        for (int l = 0; l < 2; l++) {
            int idx = t + l * 256;
            int row = idx >> 2, c4 = (idx & 3) << 2;
            float4 a = *(const float4*)(A + (size_t)(bm + row) * K + k0 + c4);
            As[row][c4 + 0] = split_tf32(a.x);
            As[row][c4 + 1] = split_tf32(a.y);
            As[row][c4 + 2] = split_tf32(a.z);
            As[row][c4 + 3] = split_tf32(a.w);
        }
        {
            int row = t >> 2, c4 = (t & 3) << 2;
            float4 b = *(const float4*)(W + (size_t)(bn + row) * K + k0 + c4);
            Bs[row][c4 + 0] = split_tf32(b.x);
            Bs[row][c4 + 1] = split_tf32(b.y);
            Bs[row][c4 + 2] = split_tf32(b.z);
            Bs[row][c4 + 3] = split_tf32(b.w);
        }
        __syncthreads();

#pragma unroll
        for (int ks = 0; ks < 2; ks++) {
            int kc = ks * 8;
            float2 af[2][4];
#pragma unroll
            for (int mt = 0; mt < 2; mt++) {
                int r0 = wm + mt * 16 + gid;
                af[mt][0] = As[r0][kc + tidg];
                af[mt][1] = As[r0 + 8][kc + tidg];
                af[mt][2] = As[r0][kc + tidg + 4];
                af[mt][3] = As[r0 + 8][kc + tidg + 4];
            }
            float2 bf[4][2];
#pragma unroll
            for (int nt = 0; nt < 4; nt++) {
                int r0 = wn + nt * 8 + gid;
                bf[nt][0] = Bs[r0][kc + tidg];
                bf[nt][1] = Bs[r0][kc + tidg + 4];
            }
#pragma unroll
            for (int mt = 0; mt < 2; mt++) {
                uint32_t ah[4], al[4];
#pragma unroll
                for (int r = 0; r < 4; r++) {
                    ah[r] = __float_as_uint(af[mt][r].x);
                    al[r] = __float_as_uint(af[mt][r].y);
                }
#pragma unroll
                for (int nt = 0; nt < 4; nt++) {
                    uint32_t bh0 = __float_as_uint(bf[nt][0].x);
                    uint32_t bh1 = __float_as_uint(bf[nt][1].x);
                    uint32_t bl0 = __float_as_uint(bf[nt][0].y);
                    uint32_t bl1 = __float_as_uint(bf[nt][1].y);
                    mma_tf32(d[mt][nt], ah[0], ah[1], ah[2], ah[3], bh0, bh1);
                    mma_tf32(d[mt][nt], ah[0], ah[1], ah[2], ah[3], bl0, bl1);
                    mma_tf32(d[mt][nt], al[0], al[1], al[2], al[3], bh0, bh1);
                }
            }
        }
        __syncthreads();
    }

#pragma unroll
    for (int mt = 0; mt < 2; mt++) {
        int r0 = bm + wm + mt * 16 + gid;
#pragma unroll
        for (int nt = 0; nt < 4; nt++) {
            int c0 = bn + wn + nt * 8 + 2 * tidg;
            float bia0 = bias[c0], bia1 = bias[c0 + 1];
#pragma unroll
            for (int half = 0; half < 2; half++) {
                int row = r0 + half * 8;
                float v0 = (d[mt][nt][half * 2 + 0] + bia0) * alpha;
                float v1 = (d[mt][nt][half * 2 + 1] + bia1) * alpha;
                if (act) {
                    v0 = 0.5f * v0 * (1.f + erff(v0 * 0.70710678118654752f));
                    v1 = 0.5f * v1 * (1.f + erff(v1 * 0.70710678118654752f));
                }
                C[(size_t)row * N + c0] = v0;
                C[(size_t)row * N + c0 + 1] = v1;
            }
        }
    }
}

__global__ void __launch_bounds__(256) k_gemm_qkv(const float* wq, const float* bq,
                                                  const float* wk, const float* bk,
                                                  const float* wv, const float* bv) {
    int z = blockIdx.z;
    const float* A = (z == 0) ? g_qin : (z == 1) ? g_kin : g_src2;
    const float* W = (z == 0) ? wq : (z == 1) ? wk : wv;
    const float* B = (z == 0) ? bq : (z == 1) ? bk : bv;
    float* C = (z == 0) ? g_qh : (z == 1) ? g_kh : g_vh;
    float alpha = (z == 0) ? 0.125f : 1.f;
    gemm_tc(A, W, B, C, D, D, alpha, 0);
}
__global__ void __launch_bounds__(256) k_gemm_o(const float* w, const float* b) {
    gemm_tc(g_att, w, b, g_proj, D, D, 1.f, 0);
}
__global__ void __launch_bounds__(256) k_gemm_f1(const float* w, const float* b) {
    gemm_tc(g_src2, w, b, g_ffn, FF, D, 1.f, 1);
}
__global__ void __launch_bounds__(256) k_gemm_f2(const float* w, const float* b) {
    gemm_tc(g_ffn, w, b, g_proj, D, FF, 1.f, 0);
}

// ---------------- V suffix sums ----------------
__global__ void k_vsuf() {
    int tb = blockIdx.x + 1;
    int h = blockIdx.y;
    int d = threadIdx.x & 63, rg = threadIdx.x >> 6;
    float s = 0.f;
    for (int m = tb * 64 + rg; m < LV; m += 4)
        s += g_vh[(size_t)m * D + h * DK + d];
    __shared__ float sh[4][64];
    sh[rg][d] = s;
    __syncthreads();
    if (rg == 0)
        g_vsuf[((size_t)h * 33 + tb) * DK + d] = sh[0][d] + sh[1][d] + sh[2][d] + sh[3][d];
}

// ---------------- tensor-core flash attention ----------------
// Block = 64 query rows. 256 threads = 8 warps, warp tile 16 rows x 32 cols.
// smem layout (floats): Ks[64][68], Vs[64][72], Ss[64][68], m_s[64], l_s[64], sc_s[64]
#define FL_STR 68
#define FL_VSTR 72
#define KS_OFF 0
#define VS_OFF (64 * FL_STR)
#define SS_OFF (VS_OFF + 64 * FL_VSTR)
#define MS_OFF (SS_OFF + 64 * FL_STR)
#define LS_OFF (MS_OFF + 64)
#define SC_OFF (LS_OFF + 64)
#define FL_SMEM_BYTES ((SC_OFF + 64) * 4)

__global__ void __launch_bounds__(256) k_flash_tc() {
    extern __shared__ float sm[];
    float* Ks = sm + KS_OFF;
    float* Vs = sm + VS_OFF;
    float* Ss = sm + SS_OFF;
    float* m_s = sm + MS_OFF;
    float* l_s = sm + LS_OFF;
    float* sc_s = sm + SC_OFF;

    int h = blockIdx.y;
    int rt = (int)gridDim.x - 1 - (int)blockIdx.x;
    int bm = rt * 64;
    int ntiles = rt + 1;
    int t = threadIdx.x;
    int warp = t >> 5, lane = t & 31;
    int gid = lane >> 2, tidg = lane & 3;
    int wm = (warp >> 1) * 16, wn = (warp & 1) * 32;

    // stage Q tile into Ss, then into per-warp register fragments (hi/lo)
#pragma unroll
    for (int l = 0; l < 4; l++) {
        int idx = t + l * 256;
        int r = idx >> 4, c4 = (idx & 15) << 2;
        float4 q = *(const float4*)(g_qh + (size_t)(bm + r) * D + h * DK + c4);
        *(float4*)&Ss[r * FL_STR + c4] = q;
    }
    if (t < 64) { m_s[t] = -1e30f; l_s[t] = 0.f; }
    __syncthreads();

    uint32_t qhr[8][4], qlr[8][4];
#pragma unroll
    for (int kc = 0; kc < 8; kc++) {
        int k0 = kc * 8;
        float v0 = Ss[(wm + gid) * FL_STR + k0 + tidg];
        float v1 = Ss[(wm + gid + 8) * FL_STR + k0 + tidg];
        float v2 = Ss[(wm + gid) * FL_STR + k0 + tidg + 4];
        float v3 = Ss[(wm + gid + 8) * FL_STR + k0 + tidg + 4];
        float2 s0 = split_tf32(v0), s1 = split_tf32(v1), s2 = split_tf32(v2), s3 = split_tf32(v3);
        qhr[kc][0] = __float_as_uint(s0.x); qlr[kc][0] = __float_as_uint(s0.y);
        qhr[kc][1] = __float_as_uint(s1.x); qlr[kc][1] = __float_as_uint(s1.y);
        qhr[kc][2] = __float_as_uint(s2.x); qlr[kc][2] = __float_as_uint(s2.y);
        qhr[kc][3] = __float_as_uint(s3.x); qlr[kc][3] = __float_as_uint(s3.y);
    }

    float acc[4][4];
#pragma unroll
    for (int nt = 0; nt < 4; nt++)
#pragma unroll
        for (int r = 0; r < 4; r++) acc[nt][r] = 0.f;

    for (int tile = 0; tile < ntiles; tile++) {
        int m0 = tile * 64;
        __syncthreads();   // protect Ks/Vs/Ss from previous iteration's readers
#pragma unroll
        for (int l = 0; l < 4; l++) {
            int idx = t + l * 256;
            int r = idx >> 4, c4 = (idx & 15) << 2;
            float4 kv = *(const float4*)(g_kh + (size_t)(m0 + r) * D + h * DK + c4);
            *(float4*)&Ks[r * FL_STR + c4] = kv;
            float4 vv = *(const float4*)(g_vh + (size_t)(m0 + r) * D + h * DK + c4);
            *(float4*)&Vs[r * FL_VSTR + c4] = vv;
        }
        __syncthreads();

        // S = Q K^T (3-term TF32)
        float sfr[4][4];
#pragma unroll
        for (int nt = 0; nt < 4; nt++)
#pragma unroll
            for (int r = 0; r < 4; r++) sfr[nt][r] = 0.f;
#pragma unroll
        for (int kc = 0; kc < 8; kc++) {
            int k0 = kc * 8;
#pragma unroll
            for (int nt = 0; nt < 4; nt++) {
                int n0 = wn + nt * 8;
                float2 b0 = split_tf32(Ks[(n0 + gid) * FL_STR + k0 + tidg]);
                float2 b1 = split_tf32(Ks[(n0 + gid) * FL_STR + k0 + tidg + 4]);
                uint32_t b0h = __float_as_uint(b0.x), b0l = __float_as_uint(b0.y);
                uint32_t b1h = __float_as_uint(b1.x), b1l = __float_as_uint(b1.y);
                mma_tf32(sfr[nt], qhr[kc][0], qhr[kc][1], qhr[kc][2], qhr[kc][3], b0h, b1h);
                mma_tf32(sfr[nt], qhr[kc][0], qhr[kc][1], qhr[kc][2], qhr[kc][3], b0l, b1l);
                mma_tf32(sfr[nt], qlr[kc][0], qlr[kc][1], qlr[kc][2], qlr[kc][3], b0h, b1h);
            }
        }
        // write S fragments to Ss
#pragma unroll
        for (int nt = 0; nt < 4; nt++) {
            int c0 = wn + nt * 8 + 2 * tidg;
            Ss[(wm + gid) * FL_STR + c0] = sfr[nt][0];
            Ss[(wm + gid) * FL_STR + c0 + 1] = sfr[nt][1];
            Ss[(wm + gid + 8) * FL_STR + c0] = sfr[nt][2];
            Ss[(wm + gid + 8) * FL_STR + c0 + 1] = sfr[nt][3];
        }
        __syncthreads();

        // softmax: 4 threads per row, 16 cols each
        {
            int row = t >> 2, seg = t & 3;
            float* rp = Ss + row * FL_STR + seg * 16;
            const float* mp = g_mask + (size_t)(bm + row) * LV + m0 + seg * 16;
            float x[16];
#pragma unroll
            for (int q4 = 0; q4 < 4; q4++) {
                float4 xv = *(float4*)(rp + q4 * 4);
                float4 mv = *(const float4*)(mp + q4 * 4);
                x[q4 * 4 + 0] = xv.x * mv.x;
                x[q4 * 4 + 1] = xv.y * mv.y;
                x[q4 * 4 + 2] = xv.z * mv.z;
                x[q4 * 4 + 3] = xv.w * mv.w;
            }
            float mx = x[0];
#pragma unroll
            for (int i = 1; i < 16; i++) mx = fmaxf(mx, x[i]);
            mx = fmaxf(mx, __shfl_xor_sync(0xffffffffu, mx, 1));
            mx = fmaxf(mx, __shfl_xor_sync(0xffffffffu, mx, 2));
            float m_old = m_s[row];
            float m_new = fmaxf(m_old, mx);
            float sum = 0.f;
#pragma unroll
            for (int i = 0; i < 16; i++) {
                x[i] = __expf(x[i] - m_new);
                sum += x[i];
            }
            sum += __shfl_xor_sync(0xffffffffu, sum, 1);
            sum += __shfl_xor_sync(0xffffffffu, sum, 2);
            float scl = __expf(m_old - m_new);
#pragma unroll
            for (int q4 = 0; q4 < 4; q4++)
                *(float4*)(rp + q4 * 4) =
                    make_float4(x[q4 * 4 + 0], x[q4 * 4 + 1], x[q4 * 4 + 2], x[q4 * 4 + 3]);
            if (seg == 0) {
                m_s[row] = m_new;
                l_s[row] = l_s[row] * scl + sum;
                sc_s[row] = scl;
            }
        }
        __syncthreads();

        // rescale O accumulators, then O += P V (3-term TF32)
        {
            float s1 = sc_s[wm + gid], s2 = sc_s[wm + gid + 8];
#pragma unroll
            for (int nt = 0; nt < 4; nt++) {
                acc[nt][0] *= s1; acc[nt][1] *= s1;
                acc[nt][2] *= s2; acc[nt][3] *= s2;
            }
        }
#pragma unroll
        for (int kc = 0; kc < 8; kc++) {
            int k0 = kc * 8;
            float2 a0 = split_tf32(Ss[(wm + gid) * FL_STR + k0 + tidg]);
            float2 a1 = split_tf32(Ss[(wm + gid + 8) * FL_STR + k0 + tidg]);
            float2 a2 = split_tf32(Ss[(wm + gid) * FL_STR + k0 + tidg + 4]);
            float2 a3 = split_tf32(Ss[(wm + gid + 8) * FL_STR + k0 + tidg + 4]);
            uint32_t ah[4] = {__float_as_uint(a0.x), __float_as_uint(a1.x),
                              __float_as_uint(a2.x), __float_as_uint(a3.x)};
            uint32_t al[4] = {__float_as_uint(a0.y), __float_as_uint(a1.y),
                              __float_as_uint(a2.y), __float_as_uint(a3.y)};
#pragma unroll
            for (int nt = 0; nt < 4; nt++) {
                int n0 = wn + nt * 8;
                float2 b0 = split_tf32(Vs[(k0 + tidg) * FL_VSTR + n0 + gid]);
                float2 b1 = split_tf32(Vs[(k0 + tidg + 4) * FL_VSTR + n0 + gid]);
                uint32_t b0h = __float_as_uint(b0.x), b0l = __float_as_uint(b0.y);
                uint32_t b1h = __float_as_uint(b1.x), b1l = __float_as_uint(b1.y);
                mma_tf32(acc[nt], ah[0], ah[1], ah[2], ah[3], b0h, b1h);
                mma_tf32(acc[nt], ah[0], ah[1], ah[2], ah[3], b0l, b1l);
                mma_tf32(acc[nt], al[0], al[1], al[2], al[3], b0h, b1h);
            }
        }
    }
    __syncthreads();

    // epilogue: analytic tail over masked-zero columns + normalize
    float nz = (float)(LV - (bm + 64));
    int tb = rt + 1;
    int r1 = wm + gid, r2 = wm + gid + 8;
    float p01 = __expf(-m_s[r1]);
    float inv1 = 1.f / (l_s[r1] + nz * p01);
    float p02 = __expf(-m_s[r2]);
    float inv2 = 1.f / (l_s[r2] + nz * p02);
#pragma unroll
    for (int nt = 0; nt < 4; nt++) {
        int c0 = wn + nt * 8 + 2 * tidg;
        float suf0 = g_vsuf[((size_t)h * 33 + tb) * DK + c0];
        float suf1 = g_vsuf[((size_t)h * 33 + tb) * DK + c0 + 1];
        g_att[(size_t)(bm + r1) * D + h * DK + c0] = (acc[nt][0] + p01 * suf0) * inv1;
        g_att[(size_t)(bm + r1) * D + h * DK + c0 + 1] = (acc[nt][1] + p01 * suf1) * inv1;
        g_att[(size_t)(bm + r2) * D + h * DK + c0] = (acc[nt][2] + p02 * suf0) * inv2;
        g_att[(size_t)(bm + r2) * D + h * DK + c0 + 1] = (acc[nt][3] + p02 * suf1) * inv2;
    }
}

// ---------------- residual + pos + LN2 ----------------
__device__ __forceinline__ float sine_pos_elem(float xe, int i) {
    const float L2_1E4 = 13.287712379549449f;
    int j = i >> 1;
    float dim = exp2f(((float)j / 256.f) * L2_1E4);
    float val = xe / dim;
    return (i & 1) ? cosf(val) : sinf(val);
}

__global__ void k_res_ln2(const float* __restrict__ w, const float* __restrict__ b) {
    int r = blockIdx.x;
    __shared__ float sh[32];
    int i0 = threadIdx.x, i1 = threadIdx.x + 256;
    size_t o = (size_t)r * D;
    float v0, v1;
    if (r < LV) {
        v0 = g_src[o + i0] + g_proj[o + i0] + g_posq[o + i0];
        v1 = g_src[o + i1] + g_proj[o + i1] + g_posq[o + i1];
    } else {
        int tt = r - LV;
        float xe = (float)(tt + 1) / (512.f + 1e-6f) * 6.283185307179586f;
        v0 = g_src[o + i0] + g_src2[o + i0] + sine_pos_elem(xe, i0);
        v1 = g_src[o + i1] + g_src2[o + i1] + sine_pos_elem(xe, i1);
    }
    float s = blk_sum(v0 + v1, sh);
    float s2 = blk_sum(v0 * v0 + v1 * v1, sh);
    float mu = s * (1.f / D);
    float var = s2 * (1.f / D) - mu * mu;
    float inv = rsqrtf(var + 1e-5f);
    g_src[o + i0] = v0;
    g_src[o + i1] = v1;
    g_src2[o + i0] = (v0 - mu) * inv * w[i0] + b[i0];
    g_src2[o + i1] = (v1 - mu) * inv * w[i1] + b[i1];
}

// ---------------- residual + LN3 + output ----------------
__global__ void k_res_ln3(const float* __restrict__ w, const float* __restrict__ b,
                          float* __restrict__ out) {
    int r = blockIdx.x;
    __shared__ float sh[32];
    int i0 = threadIdx.x, i1 = threadIdx.x + 256;
    size_t o = (size_t)r * D;
    float v0 = g_src[o + i0] + g_proj[o + i0];
    float v1 = g_src[o + i1] + g_proj[o + i1];
    float s = blk_sum(v0 + v1, sh);
    float s2 = blk_sum(v0 * v0 + v1 * v1, sh);
    float mu = s * (1.f / D);
    float var = s2 * (1.f / D) - mu * mu;
    float inv = rsqrtf(var + 1e-5f);
    out[o + i0] = (v0 - mu) * inv * w[i0] + b[i0];
    out[o + i1] = (v1 - mu) * inv * w[i1] + b[i1];
}

extern "C" void kernel_launch(void* const* d_in, const int* in_sizes, int n_in,
                              void* d_out, int out_size) {
    const float* src_vid = (const float*)d_in[0];
    const float* src_txt = (const float*)d_in[1];
    const float* ln1_w = (const float*)d_in[2];
    const float* ln1_b = (const float*)d_in[3];
    const float* wq = (const float*)d_in[4];
    const float* bq = (const float*)d_in[5];
    const float* wk = (const float*)d_in[6];
    const float* bk = (const float*)d_in[7];
    const float* wv = (const float*)d_in[8];
    const float* bv = (const float*)d_in[9];
    const float* wo = (const float*)d_in[10];
    const float* bo = (const float*)d_in[11];
    const float* lin1_w = (const float*)d_in[12];
    const float* lin1_b = (const float*)d_in[13];
    const float* lin2_w = (const float*)d_in[14];
    const float* lin2_b = (const float*)d_in[15];
    const float* ln2_w = (const float*)d_in[16];
    const float* ln2_b = (const float*)d_in[17];
    const float* ln3_w = (const float*)d_in[18];
    const float* ln3_b = (const float*)d_in[19];
    const float* learn = (const float*)d_in[20];
    float* out = (float*)d_out;

    cudaFuncSetAttribute(k_flash_tc, cudaFuncAttributeMaxDynamicSharedMemorySize, FL_SMEM_BYTES);

    k_mask<<<LV, 256>>>(learn);
    k_loss<<<1, 256>>>(out, out_size);
    k_ln1<<<LTOT, 256>>>(src_vid, src_txt, ln1_w, ln1_b);
    k_pos<<<LV, 256>>>(src_vid);

    k_gemm_qkv<<<dim3(D / 64, LV / 128, 3), 256>>>(wq, bq, wk, bk, wv, bv);

    k_vsuf<<<dim3(32, H), 256>>>();
    k_flash_tc<<<dim3(LV / 64, H), 256, FL_SMEM_BYTES>>>();

    k_gemm_o<<<dim3(D / 64, LV / 128), 256>>>(wo, bo);
    k_res_ln2<<<LTOT, 256>>>(ln2_w, ln2_b);

    k_gemm_f1<<<dim3(FF / 64, LTOT / 128), 256>>>(lin1_w, lin1_b);
    k_gemm_f2<<<dim3(D / 64, LTOT / 128), 256>>>(lin2_w, lin2_b);

    k_res_ln3<<<LTOT, 256>>>(ln3_w, ln3_b, out);
}

// round 7
// speedup vs baseline: 3.3703x; 1.5943x over previous
#include <cuda_runtime.h>
#include <cuda_bf16.h>
#include <math.h>
#include <stdint.h>

#define LV 2048
#define LT 512
#define LTOT 2560
#define D 512
#define H 8
#define DK 64
#define FF 1024

// ---------------- scratch ----------------
__device__ float g_mask[(size_t)LV * LV];
__device__ float g_partial[LV];
__device__ float g_src[(size_t)LTOT * D];
__device__ float g_src2[(size_t)LTOT * D];
__device__ float g_posq[(size_t)LV * D];
__device__ float g_qin[(size_t)LV * D];
__device__ float g_kin[(size_t)LV * D];
__device__ float g_qh[(size_t)LV * D];
__device__ float g_kh[(size_t)LV * D];
__device__ float g_vh[(size_t)LV * D];
__device__ float g_att[(size_t)LV * D];
__device__ float g_proj[(size_t)LTOT * D];
__device__ float g_ffn[(size_t)LTOT * FF];
__device__ float g_vsuf[(size_t)H * 33 * DK];
// V pre-split + transposed per head: [H][DK=64][LV/2] packed bf16 pairs (k,k+1)
__device__ uint32_t g_vth[(size_t)H * DK * (LV / 2)];
__device__ uint32_t g_vtl[(size_t)H * DK * (LV / 2)];

// ---------------- block reductions (blockDim.x == 256) ----------------
__device__ __forceinline__ float blk_sum(float v, float* sh) {
    int lane = threadIdx.x & 31, wid = threadIdx.x >> 5;
#pragma unroll
    for (int o = 16; o; o >>= 1) v += __shfl_xor_sync(0xffffffffu, v, o);
    if (lane == 0) sh[wid] = v;
    __syncthreads();
    if (threadIdx.x < 32) {
        float t = (threadIdx.x < 8) ? sh[threadIdx.x] : 0.f;
#pragma unroll
        for (int o = 4; o; o >>= 1) t += __shfl_xor_sync(0xffffffffu, t, o);
        if (threadIdx.x == 0) sh[0] = t;
    }
    __syncthreads();
    float r = sh[0];
    __syncthreads();
    return r;
}

// ---------------- mask + sparsity-loss partials ----------------
__global__ void k_mask(const float* __restrict__ learn) {
    int n = blockIdx.x;
    __shared__ float sh[32];
    const float L2G = -0.15200309344504997f;
    float psum = 0.f;
    for (int m = threadIdx.x; m < LV; m += 256) {
        float lw = learn[(size_t)n * LV + m];
        float sig = 1.f / (1.f + expf(-lw));
        float maskv;
        if (m == n) {
            maskv = 1.f;
        } else if (n > m) {
            maskv = exp2f((float)(n - m) * L2G) * sig;
            psum += sig;
        } else {
            maskv = 0.f;
            psum += sig;
        }
        g_mask[(size_t)n * LV + m] = maskv;
    }
    float t = blk_sum(psum, sh);
    if (threadIdx.x == 0) g_partial[n] = t;
}

__global__ void k_loss(float* out, int out_size) {
    __shared__ float sh[32];
    float s = 0.f;
    for (int i = threadIdx.x; i < LV; i += 256) s += g_partial[i];
    s = blk_sum(s, sh);
    if (threadIdx.x == 0 && out_size > LV * D + LT * D)
        out[(size_t)LV * D + (size_t)LT * D] = s / ((float)LV * (float)LV);
}

// ---------------- concat + LN1 ----------------
__global__ void k_ln1(const float* __restrict__ vid, const float* __restrict__ txt,
                      const float* __restrict__ w, const float* __restrict__ b) {
    int r = blockIdx.x;
    const float* x = (r < LV) ? (vid + (size_t)r * D) : (txt + (size_t)(r - LV) * D);
    __shared__ float sh[32];
    int i0 = threadIdx.x, i1 = threadIdx.x + 256;
    float v0 = x[i0], v1 = x[i1];
    float s = blk_sum(v0 + v1, sh);
    float s2 = blk_sum(v0 * v0 + v1 * v1, sh);
    float mu = s * (1.f / D);
    float var = s2 * (1.f / D) - mu * mu;
    float inv = rsqrtf(var + 1e-5f);
    size_t o = (size_t)r * D;
    g_src[o + i0] = v0;
    g_src[o + i1] = v1;
    g_src2[o + i0] = (v0 - mu) * inv * w[i0] + b[i0];
    g_src2[o + i1] = (v1 - mu) * inv * w[i1] + b[i1];
}

// ---------------- xpos positional encodings + q/k inputs ----------------
__global__ void k_pos(const float* __restrict__ vid) {
    int r = blockIdx.x;
    int j = threadIdx.x;
    const float L2_1E4 = 13.287712379549449f;
    float sj = (2.f * (float)j + 204.8f) / 716.8f;
    float scale = exp2f(((float)r / 512.f) * log2f(sj));
    float invf = exp2f(-((float)j / 256.f) * L2_1E4);
    float ang = (float)r * invf;
    float sn, cs;
    sincosf(ang, &sn, &cs);
    size_t o = (size_t)r * D + 2 * j;
    float x0 = vid[o], x1 = vid[o + 1];
    float cq = cs * scale, sq = sn * scale;
    float pq0 = x0 * cq - x1 * sq;
    float pq1 = x1 * cq + x0 * sq;
    float iscale = 1.f / scale;
    float ck = cs * iscale, sk = sn * iscale;
    float pk0 = x0 * ck - x1 * sk;
    float pk1 = x1 * ck + x0 * sk;
    g_posq[o] = pq0; g_posq[o + 1] = pq1;
    float n0 = g_src2[o], n1 = g_src2[o + 1];
    g_qin[o] = n0 + pq0; g_qin[o + 1] = n1 + pq1;
    g_kin[o] = n0 + pk0; g_kin[o + 1] = n1 + pk1;
}

// ---------------- bf16 split helpers ----------------
__device__ __forceinline__ void split2(float x, float y, uint32_t& hi, uint32_t& lo) {
    __nv_bfloat16 hx = __float2bfloat16_rn(x), hy = __float2bfloat16_rn(y);
    float lx = x - __bfloat162float(hx), ly = y - __bfloat162float(hy);
    __nv_bfloat162 hp = __halves2bfloat162(hx, hy);
    __nv_bfloat162 lp = __halves2bfloat162(__float2bfloat16_rn(lx), __float2bfloat16_rn(ly));
    hi = *(uint32_t*)&hp;
    lo = *(uint32_t*)&lp;
}

__device__ __forceinline__ void mma_bf16(float* d, uint32_t a0, uint32_t a1, uint32_t a2,
                                         uint32_t a3, uint32_t b0, uint32_t b1) {
    asm volatile(
        "mma.sync.aligned.m16n8k16.row.col.f32.bf16.bf16.f32 "
        "{%0,%1,%2,%3}, {%4,%5,%6,%7}, {%8,%9}, {%0,%1,%2,%3};"
        : "+f"(d[0]), "+f"(d[1]), "+f"(d[2]), "+f"(d[3])
        : "r"(a0), "r"(a1), "r"(a2), "r"(a3), "r"(b0), "r"(b1));
}

// ---------------- tensor-core GEMM (bf16 2-term split, 3 products) ----------------
// C(MxN) = alpha*(A(MxK) @ W(NxK)^T + bias). Block 128x64, BK=16, 256 thr, 8 warps 32x32.
__device__ __forceinline__ void gemm_tc(const float* __restrict__ A, const float* __restrict__ W,
                                        const float* __restrict__ bias, float* __restrict__ C,
                                        int N, int K, float alpha, int act) {
    __shared__ __nv_bfloat16 Ah[128][24], Al[128][24];
    __shared__ __nv_bfloat16 Bh[64][24], Bl[64][24];
    int bm = blockIdx.y * 128, bn = blockIdx.x * 64;
    int t = threadIdx.x, warp = t >> 5, lane = t & 31;
    int gid = lane >> 2, tidg = lane & 3;
    int wm = (warp >> 1) * 32, wn = (warp & 1) * 32;

    float d[2][4][4];
#pragma unroll
    for (int mt = 0; mt < 2; mt++)
#pragma unroll
        for (int nt = 0; nt < 4; nt++)
#pragma unroll
            for (int r = 0; r < 4; r++) d[mt][nt][r] = 0.f;

    for (int k0 = 0; k0 < K; k0 += 16) {
#pragma unroll
        for (int l = 0; l < 2; l++) {
            int idx = t + l * 256;
            int row = idx >> 2, c4 = (idx & 3) << 2;
            float4 a = *(const float4*)(A + (size_t)(bm + row) * K + k0 + c4);
            uint32_t h01, l01, h23, l23;
            split2(a.x, a.y, h01, l01);
            split2(a.z, a.w, h23, l23);
            *(uint32_t*)&Ah[row][c4] = h01;
            *(uint32_t*)&Ah[row][c4 + 2] = h23;
            *(uint32_t*)&Al[row][c4] = l01;
            *(uint32_t*)&Al[row][c4 + 2] = l23;
        }
        {
            int row = t >> 2, c4 = (t & 3) << 2;
            float4 b = *(const float4*)(W + (size_t)(bn + row) * K + k0 + c4);
            uint32_t h01, l01, h23, l23;
            split2(b.x, b.y, h01, l01);
            split2(b.z, b.w, h23, l23);
            *(uint32_t*)&Bh[row][c4] = h01;
            *(uint32_t*)&Bh[row][c4 + 2] = h23;
            *(uint32_t*)&Bl[row][c4] = l01;
            *(uint32_t*)&Bl[row][c4 + 2] = l23;
        }
        __syncthreads();

        uint32_t ah[2][4], al[2][4];
#pragma unroll
        for (int mt = 0; mt < 2; mt++) {
            int r0 = wm + mt * 16 + gid;
            ah[mt][0] = *(uint32_t*)&Ah[r0][2 * tidg];
            ah[mt][1] = *(uint32_t*)&Ah[r0 + 8][2 * tidg];
            ah[mt][2] = *(uint32_t*)&Ah[r0][8 + 2 * tidg];
            ah[mt][3] = *(uint32_t*)&Ah[r0 + 8][8 + 2 * tidg];
            al[mt][0] = *(uint32_t*)&Al[r0][2 * tidg];
            al[mt][1] = *(uint32_t*)&Al[r0 + 8][2 * tidg];
            al[mt][2] = *(uint32_t*)&Al[r0][8 + 2 * tidg];
            al[mt][3] = *(uint32_t*)&Al[r0 + 8][8 + 2 * tidg];
        }
#pragma unroll
        for (int nt = 0; nt < 4; nt++) {
            int n0 = wn + nt * 8 + gid;
            uint32_t bh0 = *(uint32_t*)&Bh[n0][2 * tidg];
            uint32_t bh1 = *(uint32_t*)&Bh[n0][8 + 2 * tidg];
            uint32_t bl0 = *(uint32_t*)&Bl[n0][2 * tidg];
            uint32_t bl1 = *(uint32_t*)&Bl[n0][8 + 2 * tidg];
#pragma unroll
            for (int mt = 0; mt < 2; mt++) {
                mma_bf16(d[mt][nt], ah[mt][0], ah[mt][1], ah[mt][2], ah[mt][3], bh0, bh1);
                mma_bf16(d[mt][nt], ah[mt][0], ah[mt][1], ah[mt][2], ah[mt][3], bl0, bl1);
                mma_bf16(d[mt][nt], al[mt][0], al[mt][1], al[mt][2], al[mt][3], bh0, bh1);
            }
        }
        __syncthreads();
    }

#pragma unroll
    for (int mt = 0; mt < 2; mt++) {
        int r0 = bm + wm + mt * 16 + gid;
#pragma unroll
        for (int nt = 0; nt < 4; nt++) {
            int c0 = bn + wn + nt * 8 + 2 * tidg;
            float bia0 = bias[c0], bia1 = bias[c0 + 1];
#pragma unroll
            for (int half = 0; half < 2; half++) {
                int row = r0 + half * 8;
                float v0 = (d[mt][nt][half * 2 + 0] + bia0) * alpha;
                float v1 = (d[mt][nt][half * 2 + 1] + bia1) * alpha;
                if (act) {
                    v0 = 0.5f * v0 * (1.f + erff(v0 * 0.70710678118654752f));
                    v1 = 0.5f * v1 * (1.f + erff(v1 * 0.70710678118654752f));
                }
                C[(size_t)row * N + c0] = v0;
                C[(size_t)row * N + c0 + 1] = v1;
            }
        }
    }
}

__global__ void __launch_bounds__(256) k_gemm_qkv(const float* wq, const float* bq,
                                                  const float* wk, const float* bk,
                                                  const float* wv, const float* bv) {
    int z = blockIdx.z;
    const float* A = (z == 0) ? g_qin : (z == 1) ? g_kin : g_src2;
    const float* W = (z == 0) ? wq : (z == 1) ? wk : wv;
    const float* B = (z == 0) ? bq : (z == 1) ? bk : bv;
    float* C = (z == 0) ? g_qh : (z == 1) ? g_kh : g_vh;
    float alpha = (z == 0) ? 0.125f : 1.f;
    gemm_tc(A, W, B, C, D, D, alpha, 0);
}
__global__ void __launch_bounds__(256) k_gemm_o(const float* w, const float* b) {
    gemm_tc(g_att, w, b, g_proj, D, D, 1.f, 0);
}
__global__ void __launch_bounds__(256) k_gemm_f1(const float* w, const float* b) {
    gemm_tc(g_src2, w, b, g_ffn, FF, D, 1.f, 1);
}
__global__ void __launch_bounds__(256) k_gemm_f2(const float* w, const float* b) {
    gemm_tc(g_ffn, w, b, g_proj, D, FF, 1.f, 0);
}

// ---------------- V suffix sums ----------------
__global__ void k_vsuf() {
    int tb = blockIdx.x + 1;
    int h = blockIdx.y;
    int d = threadIdx.x & 63, rg = threadIdx.x >> 6;
    float s = 0.f;
    for (int m = tb * 64 + rg; m < LV; m += 4)
        s += g_vh[(size_t)m * D + h * DK + d];
    __shared__ float sh[4][64];
    sh[rg][d] = s;
    __syncthreads();
    if (rg == 0)
        g_vsuf[((size_t)h * 33 + tb) * DK + d] = sh[0][d] + sh[1][d] + sh[2][d] + sh[3][d];
}

// ---------------- V split + transpose: g_vh -> g_vth/g_vtl ----------------
__global__ void k_vtrans() {
    __shared__ float vs[64][65];
    int m0 = blockIdx.x * 64, h = blockIdx.y;
    int t = threadIdx.x;
#pragma unroll
    for (int l = 0; l < 16; l++) {
        int idx = t + l * 256;
        int r = idx >> 6, c = idx & 63;
        vs[r][c] = g_vh[(size_t)(m0 + r) * D + h * DK + c];
    }
    __syncthreads();
    int n = t >> 2, j0 = (t & 3) * 8;
    size_t base = ((size_t)h * DK + n) * (LV / 2) + m0 / 2;
#pragma unroll
    for (int i = 0; i < 8; i++) {
        int j = j0 + i;
        uint32_t hi, lo;
        split2(vs[2 * j][n], vs[2 * j + 1][n], hi, lo);
        g_vth[base + j] = hi;
        g_vtl[base + j] = lo;
    }
}

// ---------------- tensor-core flash attention (bf16 split) ----------------
// Block = 64 query rows, 256 threads = 8 warps, warp tile 16 rows x 32 cols.
#define SS_STR 68
#define KP_STR 72   // bf16 stride (144B = 36 words)
#define VT_STR 36   // uint32 stride
#define SS_OFF 0
#define KH_OFF 4352
#define KL_OFF 6656
#define PH_OFF 8960
#define PL_OFF 11264
#define VH_OFF 13568
#define VL_OFF 15872
#define MS_OFF 18176
#define LS_OFF 18240
#define SC_OFF 18304
#define FL_SMEM_BYTES ((SC_OFF + 64) * 4)

__global__ void __launch_bounds__(256) k_flash_tc() {
    extern __shared__ float sm[];
    float* Ss = sm + SS_OFF;
    __nv_bfloat16* Kh = (__nv_bfloat16*)(sm + KH_OFF);
    __nv_bfloat16* Kl = (__nv_bfloat16*)(sm + KL_OFF);
    __nv_bfloat16* Ph = (__nv_bfloat16*)(sm + PH_OFF);
    __nv_bfloat16* Pl = (__nv_bfloat16*)(sm + PL_OFF);
    uint32_t* Vh = (uint32_t*)(sm + VH_OFF);
    uint32_t* Vl = (uint32_t*)(sm + VL_OFF);
    float* m_s = sm + MS_OFF;
    float* l_s = sm + LS_OFF;
    float* sc_s = sm + SC_OFF;

    int h = blockIdx.y;
    int rt = (int)gridDim.x - 1 - (int)blockIdx.x;
    int bm = rt * 64;
    int ntiles = rt + 1;
    int t = threadIdx.x;
    int warp = t >> 5, lane = t & 31;
    int gid = lane >> 2, tidg = lane & 3;
    int wm = (warp >> 1) * 16, wn = (warp & 1) * 32;

    // stage Q tile (fp32) into Ss, then build per-warp bf16 hi/lo fragments
#pragma unroll
    for (int l = 0; l < 4; l++) {
        int idx = t + l * 256;
        int r = idx >> 4, c4 = (idx & 15) << 2;
        float4 q = *(const float4*)(g_qh + (size_t)(bm + r) * D + h * DK + c4);
        *(float4*)&Ss[r * SS_STR + c4] = q;
    }
    if (t < 64) { m_s[t] = -1e30f; l_s[t] = 0.f; }
    __syncthreads();

    uint32_t qh[4][4], ql[4][4];
#pragma unroll
    for (int kc = 0; kc < 4; kc++) {
        int k0 = kc * 16;
        int r1 = wm + gid, r2 = r1 + 8;
        split2(Ss[r1 * SS_STR + k0 + 2 * tidg], Ss[r1 * SS_STR + k0 + 2 * tidg + 1],
               qh[kc][0], ql[kc][0]);
        split2(Ss[r2 * SS_STR + k0 + 2 * tidg], Ss[r2 * SS_STR + k0 + 2 * tidg + 1],
               qh[kc][1], ql[kc][1]);
        split2(Ss[r1 * SS_STR + k0 + 8 + 2 * tidg], Ss[r1 * SS_STR + k0 + 8 + 2 * tidg + 1],
               qh[kc][2], ql[kc][2]);
        split2(Ss[r2 * SS_STR + k0 + 8 + 2 * tidg], Ss[r2 * SS_STR + k0 + 8 + 2 * tidg + 1],
               qh[kc][3], ql[kc][3]);
    }

    float acc[4][4];
#pragma unroll
    for (int nt = 0; nt < 4; nt++)
#pragma unroll
        for (int r = 0; r < 4; r++) acc[nt][r] = 0.f;

    for (int tile = 0; tile < ntiles; tile++) {
        int m0 = tile * 64;
        __syncthreads();
        // K tile: load + split into bf16 hi/lo
#pragma unroll
        for (int l = 0; l < 4; l++) {
            int idx = t + l * 256;
            int r = idx >> 4, c4 = (idx & 15) << 2;
            float4 kv = *(const float4*)(g_kh + (size_t)(m0 + r) * D + h * DK + c4);
            uint32_t h01, l01, h23, l23;
            split2(kv.x, kv.y, h01, l01);
            split2(kv.z, kv.w, h23, l23);
            *(uint32_t*)&Kh[r * KP_STR + c4] = h01;
            *(uint32_t*)&Kh[r * KP_STR + c4 + 2] = h23;
            *(uint32_t*)&Kl[r * KP_STR + c4] = l01;
            *(uint32_t*)&Kl[r * KP_STR + c4 + 2] = l23;
        }
        // V tile: straight uint32 copies from pre-split transposed global
        {
            int n = t >> 2, j0 = (t & 3) * 8;
            size_t base = ((size_t)h * DK + n) * (LV / 2) + m0 / 2;
#pragma unroll
            for (int i = 0; i < 8; i++) {
                Vh[n * VT_STR + j0 + i] = g_vth[base + j0 + i];
                Vl[n * VT_STR + j0 + i] = g_vtl[base + j0 + i];
            }
        }
        __syncthreads();

        // S = Q K^T (3-term bf16)
        float sfr[4][4];
#pragma unroll
        for (int nt = 0; nt < 4; nt++)
#pragma unroll
            for (int r = 0; r < 4; r++) sfr[nt][r] = 0.f;
#pragma unroll
        for (int kc = 0; kc < 4; kc++) {
            int k0 = kc * 16;
#pragma unroll
            for (int nt = 0; nt < 4; nt++) {
                int n0 = (wn + nt * 8 + gid) * KP_STR;
                uint32_t bh0 = *(uint32_t*)&Kh[n0 + k0 + 2 * tidg];
                uint32_t bh1 = *(uint32_t*)&Kh[n0 + k0 + 8 + 2 * tidg];
                uint32_t bl0 = *(uint32_t*)&Kl[n0 + k0 + 2 * tidg];
                uint32_t bl1 = *(uint32_t*)&Kl[n0 + k0 + 8 + 2 * tidg];
                mma_bf16(sfr[nt], qh[kc][0], qh[kc][1], qh[kc][2], qh[kc][3], bh0, bh1);
                mma_bf16(sfr[nt], qh[kc][0], qh[kc][1], qh[kc][2], qh[kc][3], bl0, bl1);
                mma_bf16(sfr[nt], ql[kc][0], ql[kc][1], ql[kc][2], ql[kc][3], bh0, bh1);
            }
        }
#pragma unroll
        for (int nt = 0; nt < 4; nt++) {
            int c0 = wn + nt * 8 + 2 * tidg;
            Ss[(wm + gid) * SS_STR + c0] = sfr[nt][0];
            Ss[(wm + gid) * SS_STR + c0 + 1] = sfr[nt][1];
            Ss[(wm + gid + 8) * SS_STR + c0] = sfr[nt][2];
            Ss[(wm + gid + 8) * SS_STR + c0 + 1] = sfr[nt][3];
        }
        __syncthreads();

        // softmax: 4 threads per row, 16 cols each; write P split bf16
        {
            int row = t >> 2, seg = t & 3;
            float* rp = Ss + row * SS_STR + seg * 16;
            const float* mp = g_mask + (size_t)(bm + row) * LV + m0 + seg * 16;
            float x[16];
#pragma unroll
            for (int q4 = 0; q4 < 4; q4++) {
                float4 xv = *(float4*)(rp + q4 * 4);
                float4 mv = *(const float4*)(mp + q4 * 4);
                x[q4 * 4 + 0] = xv.x * mv.x;
                x[q4 * 4 + 1] = xv.y * mv.y;
                x[q4 * 4 + 2] = xv.z * mv.z;
                x[q4 * 4 + 3] = xv.w * mv.w;
            }
            float mx = x[0];
#pragma unroll
            for (int i = 1; i < 16; i++) mx = fmaxf(mx, x[i]);
            mx = fmaxf(mx, __shfl_xor_sync(0xffffffffu, mx, 1));
            mx = fmaxf(mx, __shfl_xor_sync(0xffffffffu, mx, 2));
            float m_old = m_s[row];
            float m_new = fmaxf(m_old, mx);
            float sum = 0.f;
#pragma unroll
            for (int i = 0; i < 16; i++) {
                x[i] = __expf(x[i] - m_new);
                sum += x[i];
            }
            sum += __shfl_xor_sync(0xffffffffu, sum, 1);
            sum += __shfl_xor_sync(0xffffffffu, sum, 2);
            float scl = __expf(m_old - m_new);
            int pb = row * KP_STR + seg * 16;
#pragma unroll
            for (int i = 0; i < 8; i++) {
                uint32_t hi, lo;
                split2(x[2 * i], x[2 * i + 1], hi, lo);
                *(uint32_t*)&Ph[pb + 2 * i] = hi;
                *(uint32_t*)&Pl[pb + 2 * i] = lo;
            }
            if (seg == 0) {
                m_s[row] = m_new;
                l_s[row] = l_s[row] * scl + sum;
                sc_s[row] = scl;
            }
        }
        __syncthreads();

        // rescale O, then O += P V (3-term bf16)
        {
            float s1 = sc_s[wm + gid], s2 = sc_s[wm + gid + 8];
#pragma unroll
            for (int nt = 0; nt < 4; nt++) {
                acc[nt][0] *= s1; acc[nt][1] *= s1;
                acc[nt][2] *= s2; acc[nt][3] *= s2;
            }
        }
#pragma unroll
        for (int kc = 0; kc < 4; kc++) {
            int k0 = kc * 16;
            int r1 = (wm + gid) * KP_STR, r2 = (wm + gid + 8) * KP_STR;
            uint32_t ah0 = *(uint32_t*)&Ph[r1 + k0 + 2 * tidg];
            uint32_t ah1 = *(uint32_t*)&Ph[r2 + k0 + 2 * tidg];
            uint32_t ah2 = *(uint32_t*)&Ph[r1 + k0 + 8 + 2 * tidg];
            uint32_t ah3 = *(uint32_t*)&Ph[r2 + k0 + 8 + 2 * tidg];
            uint32_t al0 = *(uint32_t*)&Pl[r1 + k0 + 2 * tidg];
            uint32_t al1 = *(uint32_t*)&Pl[r2 + k0 + 2 * tidg];
            uint32_t al2 = *(uint32_t*)&Pl[r1 + k0 + 8 + 2 * tidg];
            uint32_t al3 = *(uint32_t*)&Pl[r2 + k0 + 8 + 2 * tidg];
#pragma unroll
            for (int nt = 0; nt < 4; nt++) {
                int n0 = (wn + nt * 8 + gid) * VT_STR + k0 / 2;
                uint32_t bh0 = Vh[n0 + tidg];
                uint32_t bh1 = Vh[n0 + 4 + tidg];
                uint32_t bl0 = Vl[n0 + tidg];
                uint32_t bl1 = Vl[n0 + 4 + tidg];
                mma_bf16(acc[nt], ah0, ah1, ah2, ah3, bh0, bh1);
                mma_bf16(acc[nt], ah0, ah1, ah2, ah3, bl0, bl1);
                mma_bf16(acc[nt], al0, al1, al2, al3, bh0, bh1);
            }
        }
    }
    __syncthreads();

    // epilogue: analytic tail + normalize
    float nz = (float)(LV - (bm + 64));
    int tb = rt + 1;
    int r1 = wm + gid, r2 = wm + gid + 8;
    float p01 = __expf(-m_s[r1]);
    float inv1 = 1.f / (l_s[r1] + nz * p01);
    float p02 = __expf(-m_s[r2]);
    float inv2 = 1.f / (l_s[r2] + nz * p02);
#pragma unroll
    for (int nt = 0; nt < 4; nt++) {
        int c0 = wn + nt * 8 + 2 * tidg;
        float suf0 = g_vsuf[((size_t)h * 33 + tb) * DK + c0];
        float suf1 = g_vsuf[((size_t)h * 33 + tb) * DK + c0 + 1];
        g_att[(size_t)(bm + r1) * D + h * DK + c0] = (acc[nt][0] + p01 * suf0) * inv1;
        g_att[(size_t)(bm + r1) * D + h * DK + c0 + 1] = (acc[nt][1] + p01 * suf1) * inv1;
        g_att[(size_t)(bm + r2) * D + h * DK + c0] = (acc[nt][2] + p02 * suf0) * inv2;
        g_att[(size_t)(bm + r2) * D + h * DK + c0 + 1] = (acc[nt][3] + p02 * suf1) * inv2;
    }
}

// ---------------- residual + pos + LN2 ----------------
__device__ __forceinline__ float sine_pos_elem(float xe, int i) {
    const float L2_1E4 = 13.287712379549449f;
    int j = i >> 1;
    float dim = exp2f(((float)j / 256.f) * L2_1E4);
    float val = xe / dim;
    return (i & 1) ? cosf(val) : sinf(val);
}

__global__ void k_res_ln2(const float* __restrict__ w, const float* __restrict__ b) {
    int r = blockIdx.x;
    __shared__ float sh[32];
    int i0 = threadIdx.x, i1 = threadIdx.x + 256;
    size_t o = (size_t)r * D;
    float v0, v1;
    if (r < LV) {
        v0 = g_src[o + i0] + g_proj[o + i0] + g_posq[o + i0];
        v1 = g_src[o + i1] + g_proj[o + i1] + g_posq[o + i1];
    } else {
        int tt = r - LV;
        float xe = (float)(tt + 1) / (512.f + 1e-6f) * 6.283185307179586f;
        v0 = g_src[o + i0] + g_src2[o + i0] + sine_pos_elem(xe, i0);
        v1 = g_src[o + i1] + g_src2[o + i1] + sine_pos_elem(xe, i1);
    }
    float s = blk_sum(v0 + v1, sh);
    float s2 = blk_sum(v0 * v0 + v1 * v1, sh);
    float mu = s * (1.f / D);
    float var = s2 * (1.f / D) - mu * mu;
    float inv = rsqrtf(var + 1e-5f);
    g_src[o + i0] = v0;
    g_src[o + i1] = v1;
    g_src2[o + i0] = (v0 - mu) * inv * w[i0] + b[i0];
    g_src2[o + i1] = (v1 - mu) * inv * w[i1] + b[i1];
}

// ---------------- residual + LN3 + output ----------------
__global__ void k_res_ln3(const float* __restrict__ w, const float* __restrict__ b,
                          float* __restrict__ out) {
    int r = blockIdx.x;
    __shared__ float sh[32];
    int i0 = threadIdx.x, i1 = threadIdx.x + 256;
    size_t o = (size_t)r * D;
    float v0 = g_src[o + i0] + g_proj[o + i0];
    float v1 = g_src[o + i1] + g_proj[o + i1];
    float s = blk_sum(v0 + v1, sh);
    float s2 = blk_sum(v0 * v0 + v1 * v1, sh);
    float mu = s * (1.f / D);
    float var = s2 * (1.f / D) - mu * mu;
    float inv = rsqrtf(var + 1e-5f);
    out[o + i0] = (v0 - mu) * inv * w[i0] + b[i0];
    out[o + i1] = (v1 - mu) * inv * w[i1] + b[i1];
}

extern "C" void kernel_launch(void* const* d_in, const int* in_sizes, int n_in,
                              void* d_out, int out_size) {
    const float* src_vid = (const float*)d_in[0];
    const float* src_txt = (const float*)d_in[1];
    const float* ln1_w = (const float*)d_in[2];
    const float* ln1_b = (const float*)d_in[3];
    const float* wq = (const float*)d_in[4];
    const float* bq = (const float*)d_in[5];
    const float* wk = (const float*)d_in[6];
    const float* bk = (const float*)d_in[7];
    const float* wv = (const float*)d_in[8];
    const float* bv = (const float*)d_in[9];
    const float* wo = (const float*)d_in[10];
    const float* bo = (const float*)d_in[11];
    const float* lin1_w = (const float*)d_in[12];
    const float* lin1_b = (const float*)d_in[13];
    const float* lin2_w = (const float*)d_in[14];
    const float* lin2_b = (const float*)d_in[15];
    const float* ln2_w = (const float*)d_in[16];
    const float* ln2_b = (const float*)d_in[17];
    const float* ln3_w = (const float*)d_in[18];
    const float* ln3_b = (const float*)d_in[19];
    const float* learn = (const float*)d_in[20];
    float* out = (float*)d_out;

    cudaFuncSetAttribute(k_flash_tc, cudaFuncAttributeMaxDynamicSharedMemorySize, FL_SMEM_BYTES);

    k_mask<<<LV, 256>>>(learn);
    k_loss<<<1, 256>>>(out, out_size);
    k_ln1<<<LTOT, 256>>>(src_vid, src_txt, ln1_w, ln1_b);
    k_pos<<<LV, 256>>>(src_vid);

    k_gemm_qkv<<<dim3(D / 64, LV / 128, 3), 256>>>(wq, bq, wk, bk, wv, bv);

    k_vsuf<<<dim3(32, H), 256>>>();
    k_vtrans<<<dim3(LV / 64, H), 256>>>();
    k_flash_tc<<<dim3(LV / 64, H), 256, FL_SMEM_BYTES>>>();

    k_gemm_o<<<dim3(D / 64, LV / 128), 256>>>(wo, bo);
    k_res_ln2<<<LTOT, 256>>>(ln2_w, ln2_b);

    k_gemm_f1<<<dim3(FF / 64, LTOT / 128), 256>>>(lin1_w, lin1_b);
    k_gemm_f2<<<dim3(D / 64, LTOT / 128), 256>>>(lin2_w, lin2_b);

    k_res_ln3<<<LTOT, 256>>>(ln3_w, ln3_b, out);
}

// round 8
// speedup vs baseline: 4.0526x; 1.2024x over previous
#include <cuda_runtime.h>
#include <cuda_bf16.h>
#include <math.h>
#include <stdint.h>

#define LV 2048
#define LT 512
#define LTOT 2560
#define D 512
#define H 8
#define DK 64
#define FF 1024

// ---------------- scratch ----------------
__device__ float g_mask[(size_t)LV * LV];
__device__ float g_partial[LV];
__device__ float g_src[(size_t)LTOT * D];
__device__ float g_src2[(size_t)LTOT * D];
__device__ float g_posq[(size_t)LV * D];
__device__ float g_qin[(size_t)LV * D];
__device__ float g_kin[(size_t)LV * D];
__device__ float g_qh[(size_t)LV * D];
__device__ float g_kh[(size_t)LV * D];
__device__ float g_vh[(size_t)LV * D];
__device__ float g_att[(size_t)LV * D];
__device__ float g_proj[(size_t)LTOT * D];
__device__ float g_ffn[(size_t)LTOT * FF];
__device__ float g_vsuf[(size_t)H * 33 * DK];
// V pre-split + transposed per head: [H][DK=64][LV/2] packed bf16 pairs
__device__ uint32_t g_vth[(size_t)H * DK * (LV / 2)];
__device__ uint32_t g_vtl[(size_t)H * DK * (LV / 2)];
// split-flash partials: [H][32 row tiles][4 chunks][64x64] + m/l [..][64]
__device__ float g_Opart[(size_t)H * 32 * 4 * 64 * 64];
__device__ float g_mpart[(size_t)H * 32 * 4 * 64];
__device__ float g_lpart[(size_t)H * 32 * 4 * 64];

// ---------------- block reductions (blockDim.x == 256) ----------------
__device__ __forceinline__ float blk_sum(float v, float* sh) {
    int lane = threadIdx.x & 31, wid = threadIdx.x >> 5;
#pragma unroll
    for (int o = 16; o; o >>= 1) v += __shfl_xor_sync(0xffffffffu, v, o);
    if (lane == 0) sh[wid] = v;
    __syncthreads();
    if (threadIdx.x < 32) {
        float t = (threadIdx.x < 8) ? sh[threadIdx.x] : 0.f;
#pragma unroll
        for (int o = 4; o; o >>= 1) t += __shfl_xor_sync(0xffffffffu, t, o);
        if (threadIdx.x == 0) sh[0] = t;
    }
    __syncthreads();
    float r = sh[0];
    __syncthreads();
    return r;
}

// ---------------- mask + sparsity-loss partials ----------------
__global__ void k_mask(const float* __restrict__ learn) {
    int n = blockIdx.x;
    __shared__ float sh[32];
    const float L2G = -0.15200309344504997f;
    float psum = 0.f;
    for (int m = threadIdx.x; m < LV; m += 256) {
        float lw = learn[(size_t)n * LV + m];
        float sig = 1.f / (1.f + expf(-lw));
        float maskv;
        if (m == n) {
            maskv = 1.f;
        } else if (n > m) {
            maskv = exp2f((float)(n - m) * L2G) * sig;
            psum += sig;
        } else {
            maskv = 0.f;
            psum += sig;
        }
        g_mask[(size_t)n * LV + m] = maskv;
    }
    float t = blk_sum(psum, sh);
    if (threadIdx.x == 0) g_partial[n] = t;
}

__global__ void k_loss(float* out, int out_size) {
    __shared__ float sh[32];
    float s = 0.f;
    for (int i = threadIdx.x; i < LV; i += 256) s += g_partial[i];
    s = blk_sum(s, sh);
    if (threadIdx.x == 0 && out_size > LV * D + LT * D)
        out[(size_t)LV * D + (size_t)LT * D] = s / ((float)LV * (float)LV);
}

// ---------------- concat + LN1 ----------------
__global__ void k_ln1(const float* __restrict__ vid, const float* __restrict__ txt,
                      const float* __restrict__ w, const float* __restrict__ b) {
    int r = blockIdx.x;
    const float* x = (r < LV) ? (vid + (size_t)r * D) : (txt + (size_t)(r - LV) * D);
    __shared__ float sh[32];
    int i0 = threadIdx.x, i1 = threadIdx.x + 256;
    float v0 = x[i0], v1 = x[i1];
    float s = blk_sum(v0 + v1, sh);
    float s2 = blk_sum(v0 * v0 + v1 * v1, sh);
    float mu = s * (1.f / D);
    float var = s2 * (1.f / D) - mu * mu;
    float inv = rsqrtf(var + 1e-5f);
    size_t o = (size_t)r * D;
    g_src[o + i0] = v0;
    g_src[o + i1] = v1;
    g_src2[o + i0] = (v0 - mu) * inv * w[i0] + b[i0];
    g_src2[o + i1] = (v1 - mu) * inv * w[i1] + b[i1];
}

// ---------------- xpos positional encodings + q/k inputs ----------------
__global__ void k_pos(const float* __restrict__ vid) {
    int r = blockIdx.x;
    int j = threadIdx.x;
    const float L2_1E4 = 13.287712379549449f;
    float sj = (2.f * (float)j + 204.8f) / 716.8f;
    float scale = exp2f(((float)r / 512.f) * log2f(sj));
    float invf = exp2f(-((float)j / 256.f) * L2_1E4);
    float ang = (float)r * invf;
    float sn, cs;
    sincosf(ang, &sn, &cs);
    size_t o = (size_t)r * D + 2 * j;
    float x0 = vid[o], x1 = vid[o + 1];
    float cq = cs * scale, sq = sn * scale;
    float pq0 = x0 * cq - x1 * sq;
    float pq1 = x1 * cq + x0 * sq;
    float iscale = 1.f / scale;
    float ck = cs * iscale, sk = sn * iscale;
    float pk0 = x0 * ck - x1 * sk;
    float pk1 = x1 * ck + x0 * sk;
    g_posq[o] = pq0; g_posq[o + 1] = pq1;
    float n0 = g_src2[o], n1 = g_src2[o + 1];
    g_qin[o] = n0 + pq0; g_qin[o + 1] = n1 + pq1;
    g_kin[o] = n0 + pk0; g_kin[o + 1] = n1 + pk1;
}

// ---------------- bf16 split helpers ----------------
__device__ __forceinline__ void split2(float x, float y, uint32_t& hi, uint32_t& lo) {
    __nv_bfloat16 hx = __float2bfloat16_rn(x), hy = __float2bfloat16_rn(y);
    float lx = x - __bfloat162float(hx), ly = y - __bfloat162float(hy);
    __nv_bfloat162 hp = __halves2bfloat162(hx, hy);
    __nv_bfloat162 lp = __halves2bfloat162(__float2bfloat16_rn(lx), __float2bfloat16_rn(ly));
    hi = *(uint32_t*)&hp;
    lo = *(uint32_t*)&lp;
}

__device__ __forceinline__ void mma_bf16(float* d, uint32_t a0, uint32_t a1, uint32_t a2,
                                         uint32_t a3, uint32_t b0, uint32_t b1) {
    asm volatile(
        "mma.sync.aligned.m16n8k16.row.col.f32.bf16.bf16.f32 "
        "{%0,%1,%2,%3}, {%4,%5,%6,%7}, {%8,%9}, {%0,%1,%2,%3};"
        : "+f"(d[0]), "+f"(d[1]), "+f"(d[2]), "+f"(d[3])
        : "r"(a0), "r"(a1), "r"(a2), "r"(a3), "r"(b0), "r"(b1));
}

// ---------------- tensor-core GEMM (bf16 split, register prefetch) ----------------
__device__ __forceinline__ void gemm_tc(const float* __restrict__ A, const float* __restrict__ W,
                                        const float* __restrict__ bias, float* __restrict__ C,
                                        int N, int K, float alpha, int act) {
    __shared__ __nv_bfloat16 Ah[128][24], Al[128][24];
    __shared__ __nv_bfloat16 Bh[64][24], Bl[64][24];
    int bm = blockIdx.y * 128, bn = blockIdx.x * 64;
    int t = threadIdx.x, warp = t >> 5, lane = t & 31;
    int gid = lane >> 2, tidg = lane & 3;
    int wm = (warp >> 1) * 32, wn = (warp & 1) * 32;

    int rowA0 = t >> 2, rowA1 = (t >> 2) + 64, c4 = (t & 3) << 2;
    int rowB = t >> 2;

    float d[2][4][4];
#pragma unroll
    for (int mt = 0; mt < 2; mt++)
#pragma unroll
        for (int nt = 0; nt < 4; nt++)
#pragma unroll
            for (int r = 0; r < 4; r++) d[mt][nt][r] = 0.f;

    float4 pa0 = *(const float4*)(A + (size_t)(bm + rowA0) * K + c4);
    float4 pa1 = *(const float4*)(A + (size_t)(bm + rowA1) * K + c4);
    float4 pb = *(const float4*)(W + (size_t)(bn + rowB) * K + c4);

    for (int k0 = 0; k0 < K; k0 += 16) {
        {
            uint32_t h01, l01, h23, l23;
            split2(pa0.x, pa0.y, h01, l01);
            split2(pa0.z, pa0.w, h23, l23);
            *(uint32_t*)&Ah[rowA0][c4] = h01;
            *(uint32_t*)&Ah[rowA0][c4 + 2] = h23;
            *(uint32_t*)&Al[rowA0][c4] = l01;
            *(uint32_t*)&Al[rowA0][c4 + 2] = l23;
            split2(pa1.x, pa1.y, h01, l01);
            split2(pa1.z, pa1.w, h23, l23);
            *(uint32_t*)&Ah[rowA1][c4] = h01;
            *(uint32_t*)&Ah[rowA1][c4 + 2] = h23;
            *(uint32_t*)&Al[rowA1][c4] = l01;
            *(uint32_t*)&Al[rowA1][c4 + 2] = l23;
            split2(pb.x, pb.y, h01, l01);
            split2(pb.z, pb.w, h23, l23);
            *(uint32_t*)&Bh[rowB][c4] = h01;
            *(uint32_t*)&Bh[rowB][c4 + 2] = h23;
            *(uint32_t*)&Bl[rowB][c4] = l01;
            *(uint32_t*)&Bl[rowB][c4 + 2] = l23;
        }
        __syncthreads();
        if (k0 + 16 < K) {
            pa0 = *(const float4*)(A + (size_t)(bm + rowA0) * K + k0 + 16 + c4);
            pa1 = *(const float4*)(A + (size_t)(bm + rowA1) * K + k0 + 16 + c4);
            pb = *(const float4*)(W + (size_t)(bn + rowB) * K + k0 + 16 + c4);
        }

        uint32_t ah[2][4], al[2][4];
#pragma unroll
        for (int mt = 0; mt < 2; mt++) {
            int r0 = wm + mt * 16 + gid;
            ah[mt][0] = *(uint32_t*)&Ah[r0][2 * tidg];
            ah[mt][1] = *(uint32_t*)&Ah[r0 + 8][2 * tidg];
            ah[mt][2] = *(uint32_t*)&Ah[r0][8 + 2 * tidg];
            ah[mt][3] = *(uint32_t*)&Ah[r0 + 8][8 + 2 * tidg];
            al[mt][0] = *(uint32_t*)&Al[r0][2 * tidg];
            al[mt][1] = *(uint32_t*)&Al[r0 + 8][2 * tidg];
            al[mt][2] = *(uint32_t*)&Al[r0][8 + 2 * tidg];
            al[mt][3] = *(uint32_t*)&Al[r0 + 8][8 + 2 * tidg];
        }
#pragma unroll
        for (int nt = 0; nt < 4; nt++) {
            int n0 = wn + nt * 8 + gid;
            uint32_t bh0 = *(uint32_t*)&Bh[n0][2 * tidg];
            uint32_t bh1 = *(uint32_t*)&Bh[n0][8 + 2 * tidg];
            uint32_t bl0 = *(uint32_t*)&Bl[n0][2 * tidg];
            uint32_t bl1 = *(uint32_t*)&Bl[n0][8 + 2 * tidg];
#pragma unroll
            for (int mt = 0; mt < 2; mt++) {
                mma_bf16(d[mt][nt], ah[mt][0], ah[mt][1], ah[mt][2], ah[mt][3], bh0, bh1);
                mma_bf16(d[mt][nt], ah[mt][0], ah[mt][1], ah[mt][2], ah[mt][3], bl0, bl1);
                mma_bf16(d[mt][nt], al[mt][0], al[mt][1], al[mt][2], al[mt][3], bh0, bh1);
            }
        }
        __syncthreads();
    }

#pragma unroll
    for (int mt = 0; mt < 2; mt++) {
        int r0 = bm + wm + mt * 16 + gid;
#pragma unroll
        for (int nt = 0; nt < 4; nt++) {
            int c0 = bn + wn + nt * 8 + 2 * tidg;
            float bia0 = bias[c0], bia1 = bias[c0 + 1];
#pragma unroll
            for (int half = 0; half < 2; half++) {
                int row = r0 + half * 8;
                float v0 = (d[mt][nt][half * 2 + 0] + bia0) * alpha;
                float v1 = (d[mt][nt][half * 2 + 1] + bia1) * alpha;
                if (act) {
                    v0 = 0.5f * v0 * (1.f + erff(v0 * 0.70710678118654752f));
                    v1 = 0.5f * v1 * (1.f + erff(v1 * 0.70710678118654752f));
                }
                C[(size_t)row * N + c0] = v0;
                C[(size_t)row * N + c0 + 1] = v1;
            }
        }
    }
}

__global__ void __launch_bounds__(256) k_gemm_qkv(const float* wq, const float* bq,
                                                  const float* wk, const float* bk,
                                                  const float* wv, const float* bv) {
    int z = blockIdx.z;
    const float* A = (z == 0) ? g_qin : (z == 1) ? g_kin : g_src2;
    const float* W = (z == 0) ? wq : (z == 1) ? wk : wv;
    const float* B = (z == 0) ? bq : (z == 1) ? bk : bv;
    float* C = (z == 0) ? g_qh : (z == 1) ? g_kh : g_vh;
    float alpha = (z == 0) ? 0.125f : 1.f;
    gemm_tc(A, W, B, C, D, D, alpha, 0);
}
__global__ void __launch_bounds__(256) k_gemm_o(const float* w, const float* b) {
    gemm_tc(g_att, w, b, g_proj, D, D, 1.f, 0);
}
__global__ void __launch_bounds__(256) k_gemm_f1(const float* w, const float* b) {
    gemm_tc(g_src2, w, b, g_ffn, FF, D, 1.f, 1);
}
__global__ void __launch_bounds__(256) k_gemm_f2(const float* w, const float* b) {
    gemm_tc(g_ffn, w, b, g_proj, D, FF, 1.f, 0);
}

// ---------------- V suffix sums ----------------
__global__ void k_vsuf() {
    int tb = blockIdx.x + 1;
    int h = blockIdx.y;
    int d = threadIdx.x & 63, rg = threadIdx.x >> 6;
    float s = 0.f;
    for (int m = tb * 64 + rg; m < LV; m += 4)
        s += g_vh[(size_t)m * D + h * DK + d];
    __shared__ float sh[4][64];
    sh[rg][d] = s;
    __syncthreads();
    if (rg == 0)
        g_vsuf[((size_t)h * 33 + tb) * DK + d] = sh[0][d] + sh[1][d] + sh[2][d] + sh[3][d];
}

// ---------------- V split + transpose ----------------
__global__ void k_vtrans() {
    __shared__ float vs[64][65];
    int m0 = blockIdx.x * 64, h = blockIdx.y;
    int t = threadIdx.x;
#pragma unroll
    for (int l = 0; l < 16; l++) {
        int idx = t + l * 256;
        int r = idx >> 6, c = idx & 63;
        vs[r][c] = g_vh[(size_t)(m0 + r) * D + h * DK + c];
    }
    __syncthreads();
    int n = t >> 2, j0 = (t & 3) * 8;
    size_t base = ((size_t)h * DK + n) * (LV / 2) + m0 / 2;
#pragma unroll
    for (int i = 0; i < 8; i++) {
        int j = j0 + i;
        uint32_t hi, lo;
        split2(vs[2 * j][n], vs[2 * j + 1][n], hi, lo);
        g_vth[base + j] = hi;
        g_vtl[base + j] = lo;
    }
}

// ---------------- split-K tensor-core flash attention ----------------
#define SS_STR 68
#define KP_STR 72
#define VT_STR 36
#define SS_OFF 0
#define KH_OFF 4352
#define KL_OFF 6656
#define PH_OFF 8960
#define PL_OFF 11264
#define VH_OFF 13568
#define VL_OFF 15872
#define MS_OFF 18176
#define LS_OFF 18240
#define SC_OFF 18304
#define FL_SMEM_BYTES ((SC_OFF + 64) * 4)

__global__ void __launch_bounds__(256) k_flash_chunk() {
    extern __shared__ float sm[];
    float* Ss = sm + SS_OFF;
    __nv_bfloat16* Kh = (__nv_bfloat16*)(sm + KH_OFF);
    __nv_bfloat16* Kl = (__nv_bfloat16*)(sm + KL_OFF);
    __nv_bfloat16* Ph = (__nv_bfloat16*)(sm + PH_OFF);
    __nv_bfloat16* Pl = (__nv_bfloat16*)(sm + PL_OFF);
    uint32_t* Vh = (uint32_t*)(sm + VH_OFF);
    uint32_t* Vl = (uint32_t*)(sm + VL_OFF);
    float* m_s = sm + MS_OFF;
    float* l_s = sm + LS_OFF;
    float* sc_s = sm + SC_OFF;

    int h = blockIdx.y;
    int c = blockIdx.x;
    int rt, ci;
    if (c < 8) { rt = c; ci = 0; }
    else if (c < 24) { rt = 8 + (c - 8) / 2; ci = (c - 8) % 2; }
    else if (c < 48) { rt = 16 + (c - 24) / 3; ci = (c - 24) % 3; }
    else { rt = 24 + (c - 48) / 4; ci = (c - 48) % 4; }
    int nch = rt / 8 + 1;
    int ntot = rt + 1;
    int tpc = (ntot + nch - 1) / nch;
    int tile0 = ci * tpc;
    int tile1 = min(tile0 + tpc, ntot);
    int bm = rt * 64;

    int t = threadIdx.x;
    int warp = t >> 5, lane = t & 31;
    int gid = lane >> 2, tidg = lane & 3;
    int wm = (warp >> 1) * 16, wn = (warp & 1) * 32;

    // stage Q tile into Ss, build bf16 hi/lo fragments
#pragma unroll
    for (int l = 0; l < 4; l++) {
        int idx = t + l * 256;
        int r = idx >> 4, c4 = (idx & 15) << 2;
        float4 q = *(const float4*)(g_qh + (size_t)(bm + r) * D + h * DK + c4);
        *(float4*)&Ss[r * SS_STR + c4] = q;
    }
    if (t < 64) { m_s[t] = -1e30f; l_s[t] = 0.f; }
    __syncthreads();

    uint32_t qh[4][4], ql[4][4];
#pragma unroll
    for (int kc = 0; kc < 4; kc++) {
        int k0 = kc * 16;
        int r1 = wm + gid, r2 = r1 + 8;
        split2(Ss[r1 * SS_STR + k0 + 2 * tidg], Ss[r1 * SS_STR + k0 + 2 * tidg + 1],
               qh[kc][0], ql[kc][0]);
        split2(Ss[r2 * SS_STR + k0 + 2 * tidg], Ss[r2 * SS_STR + k0 + 2 * tidg + 1],
               qh[kc][1], ql[kc][1]);
        split2(Ss[r1 * SS_STR + k0 + 8 + 2 * tidg], Ss[r1 * SS_STR + k0 + 8 + 2 * tidg + 1],
               qh[kc][2], ql[kc][2]);
        split2(Ss[r2 * SS_STR + k0 + 8 + 2 * tidg], Ss[r2 * SS_STR + k0 + 8 + 2 * tidg + 1],
               qh[kc][3], ql[kc][3]);
    }

    float acc[4][4];
#pragma unroll
    for (int nt = 0; nt < 4; nt++)
#pragma unroll
        for (int r = 0; r < 4; r++) acc[nt][r] = 0.f;

    for (int tile = tile0; tile < tile1; tile++) {
        int m0 = tile * 64;
        __syncthreads();
#pragma unroll
        for (int l = 0; l < 4; l++) {
            int idx = t + l * 256;
            int r = idx >> 4, c4 = (idx & 15) << 2;
            float4 kv = *(const float4*)(g_kh + (size_t)(m0 + r) * D + h * DK + c4);
            uint32_t h01, l01, h23, l23;
            split2(kv.x, kv.y, h01, l01);
            split2(kv.z, kv.w, h23, l23);
            *(uint32_t*)&Kh[r * KP_STR + c4] = h01;
            *(uint32_t*)&Kh[r * KP_STR + c4 + 2] = h23;
            *(uint32_t*)&Kl[r * KP_STR + c4] = l01;
            *(uint32_t*)&Kl[r * KP_STR + c4 + 2] = l23;
        }
        {
            int n = t >> 2, j0 = (t & 3) * 8;
            size_t base = ((size_t)h * DK + n) * (LV / 2) + m0 / 2;
#pragma unroll
            for (int i = 0; i < 8; i++) {
                Vh[n * VT_STR + j0 + i] = g_vth[base + j0 + i];
                Vl[n * VT_STR + j0 + i] = g_vtl[base + j0 + i];
            }
        }
        __syncthreads();

        // S = Q K^T (3-term bf16)
        float sfr[4][4];
#pragma unroll
        for (int nt = 0; nt < 4; nt++)
#pragma unroll
            for (int r = 0; r < 4; r++) sfr[nt][r] = 0.f;
#pragma unroll
        for (int kc = 0; kc < 4; kc++) {
            int k0 = kc * 16;
#pragma unroll
            for (int nt = 0; nt < 4; nt++) {
                int n0 = (wn + nt * 8 + gid) * KP_STR;
                uint32_t bh0 = *(uint32_t*)&Kh[n0 + k0 + 2 * tidg];
                uint32_t bh1 = *(uint32_t*)&Kh[n0 + k0 + 8 + 2 * tidg];
                uint32_t bl0 = *(uint32_t*)&Kl[n0 + k0 + 2 * tidg];
                uint32_t bl1 = *(uint32_t*)&Kl[n0 + k0 + 8 + 2 * tidg];
                mma_bf16(sfr[nt], qh[kc][0], qh[kc][1], qh[kc][2], qh[kc][3], bh0, bh1);
                mma_bf16(sfr[nt], qh[kc][0], qh[kc][1], qh[kc][2], qh[kc][3], bl0, bl1);
                mma_bf16(sfr[nt], ql[kc][0], ql[kc][1], ql[kc][2], ql[kc][3], bh0, bh1);
            }
        }
#pragma unroll
        for (int nt = 0; nt < 4; nt++) {
            int c0 = wn + nt * 8 + 2 * tidg;
            Ss[(wm + gid) * SS_STR + c0] = sfr[nt][0];
            Ss[(wm + gid) * SS_STR + c0 + 1] = sfr[nt][1];
            Ss[(wm + gid + 8) * SS_STR + c0] = sfr[nt][2];
            Ss[(wm + gid + 8) * SS_STR + c0 + 1] = sfr[nt][3];
        }
        __syncthreads();

        // softmax: 4 threads per row; write P split bf16
        {
            int row = t >> 2, seg = t & 3;
            float* rp = Ss + row * SS_STR + seg * 16;
            const float* mp = g_mask + (size_t)(bm + row) * LV + m0 + seg * 16;
            float x[16];
#pragma unroll
            for (int q4 = 0; q4 < 4; q4++) {
                float4 xv = *(float4*)(rp + q4 * 4);
                float4 mv = *(const float4*)(mp + q4 * 4);
                x[q4 * 4 + 0] = xv.x * mv.x;
                x[q4 * 4 + 1] = xv.y * mv.y;
                x[q4 * 4 + 2] = xv.z * mv.z;
                x[q4 * 4 + 3] = xv.w * mv.w;
            }
            float mx = x[0];
#pragma unroll
            for (int i = 1; i < 16; i++) mx = fmaxf(mx, x[i]);
            mx = fmaxf(mx, __shfl_xor_sync(0xffffffffu, mx, 1));
            mx = fmaxf(mx, __shfl_xor_sync(0xffffffffu, mx, 2));
            float m_old = m_s[row];
            float m_new = fmaxf(m_old, mx);
            float sum = 0.f;
#pragma unroll
            for (int i = 0; i < 16; i++) {
                x[i] = __expf(x[i] - m_new);
                sum += x[i];
            }
            sum += __shfl_xor_sync(0xffffffffu, sum, 1);
            sum += __shfl_xor_sync(0xffffffffu, sum, 2);
            float scl = __expf(m_old - m_new);
            int pb = row * KP_STR + seg * 16;
#pragma unroll
            for (int i = 0; i < 8; i++) {
                uint32_t hi, lo;
                split2(x[2 * i], x[2 * i + 1], hi, lo);
                *(uint32_t*)&Ph[pb + 2 * i] = hi;
                *(uint32_t*)&Pl[pb + 2 * i] = lo;
            }
            if (seg == 0) {
                m_s[row] = m_new;
                l_s[row] = l_s[row] * scl + sum;
                sc_s[row] = scl;
            }
        }
        __syncthreads();

        // rescale O, then O += P V
        {
            float s1 = sc_s[wm + gid], s2 = sc_s[wm + gid + 8];
#pragma unroll
            for (int nt = 0; nt < 4; nt++) {
                acc[nt][0] *= s1; acc[nt][1] *= s1;
                acc[nt][2] *= s2; acc[nt][3] *= s2;
            }
        }
#pragma unroll
        for (int kc = 0; kc < 4; kc++) {
            int k0 = kc * 16;
            int r1 = (wm + gid) * KP_STR, r2 = (wm + gid + 8) * KP_STR;
            uint32_t ah0 = *(uint32_t*)&Ph[r1 + k0 + 2 * tidg];
            uint32_t ah1 = *(uint32_t*)&Ph[r2 + k0 + 2 * tidg];
            uint32_t ah2 = *(uint32_t*)&Ph[r1 + k0 + 8 + 2 * tidg];
            uint32_t ah3 = *(uint32_t*)&Ph[r2 + k0 + 8 + 2 * tidg];
            uint32_t al0 = *(uint32_t*)&Pl[r1 + k0 + 2 * tidg];
            uint32_t al1 = *(uint32_t*)&Pl[r2 + k0 + 2 * tidg];
            uint32_t al2 = *(uint32_t*)&Pl[r1 + k0 + 8 + 2 * tidg];
            uint32_t al3 = *(uint32_t*)&Pl[r2 + k0 + 8 + 2 * tidg];
#pragma unroll
            for (int nt = 0; nt < 4; nt++) {
                int n0 = (wn + nt * 8 + gid) * VT_STR + k0 / 2;
                uint32_t bh0 = Vh[n0 + tidg];
                uint32_t bh1 = Vh[n0 + 4 + tidg];
                uint32_t bl0 = Vl[n0 + tidg];
                uint32_t bl1 = Vl[n0 + 4 + tidg];
                mma_bf16(acc[nt], ah0, ah1, ah2, ah3, bh0, bh1);
                mma_bf16(acc[nt], ah0, ah1, ah2, ah3, bl0, bl1);
                mma_bf16(acc[nt], al0, al1, al2, al3, bh0, bh1);
            }
        }
    }
    __syncthreads();

    // write partials (unnormalized, chunk-local m/l)
    size_t obase = (((size_t)h * 32 + rt) * 4 + ci) * 4096;
    int r1 = wm + gid, r2 = wm + gid + 8;
#pragma unroll
    for (int nt = 0; nt < 4; nt++) {
        int c0 = wn + nt * 8 + 2 * tidg;
        g_Opart[obase + r1 * 64 + c0] = acc[nt][0];
        g_Opart[obase + r1 * 64 + c0 + 1] = acc[nt][1];
        g_Opart[obase + r2 * 64 + c0] = acc[nt][2];
        g_Opart[obase + r2 * 64 + c0 + 1] = acc[nt][3];
    }
    if (t < 64) {
        size_t mbase = (((size_t)h * 32 + rt) * 4 + ci) * 64 + t;
        g_mpart[mbase] = m_s[t];
        g_lpart[mbase] = l_s[t];
    }
}

// ---------------- merge partials + analytic tail + normalize ----------------
__global__ void __launch_bounds__(256) k_fmerge() {
    int rt = blockIdx.x, h = blockIdx.y;
    int nch = rt / 8 + 1;
    int bm = rt * 64;
    int t = threadIdx.x;
    int row = t >> 2, seg = t & 3;

    size_t pbase = ((size_t)h * 32 + rt) * 4;
    float mv[4], lv[4];
    float mstar = -1e30f;
#pragma unroll
    for (int ci = 0; ci < 4; ci++) {
        if (ci < nch) {
            mv[ci] = g_mpart[(pbase + ci) * 64 + row];
            lv[ci] = g_lpart[(pbase + ci) * 64 + row];
            mstar = fmaxf(mstar, mv[ci]);
        }
    }
    float p0 = __expf(-mstar);   // weight of masked-zero tail columns
    float nz = (float)(LV - (bm + 64));
    float lstar = nz * p0;
    float w[4];
#pragma unroll
    for (int ci = 0; ci < 4; ci++) {
        if (ci < nch) {
            w[ci] = __expf(mv[ci] - mstar);
            lstar += lv[ci] * w[ci];
        }
    }
    float inv = 1.f / lstar;

    int tb = rt + 1;
    const float* suf = g_vsuf + ((size_t)h * 33 + tb) * DK + seg * 16;
    float o[16];
#pragma unroll
    for (int q4 = 0; q4 < 4; q4++) {
        float4 sv = *(const float4*)(suf + q4 * 4);
        o[q4 * 4 + 0] = p0 * sv.x;
        o[q4 * 4 + 1] = p0 * sv.y;
        o[q4 * 4 + 2] = p0 * sv.z;
        o[q4 * 4 + 3] = p0 * sv.w;
    }
#pragma unroll
    for (int ci = 0; ci < 4; ci++) {
        if (ci < nch) {
            const float* op = g_Opart + (pbase + ci) * 4096 + row * 64 + seg * 16;
            float wc = w[ci];
#pragma unroll
            for (int q4 = 0; q4 < 4; q4++) {
                float4 ov = *(const float4*)(op + q4 * 4);
                o[q4 * 4 + 0] += wc * ov.x;
                o[q4 * 4 + 1] += wc * ov.y;
                o[q4 * 4 + 2] += wc * ov.z;
                o[q4 * 4 + 3] += wc * ov.w;
            }
        }
    }
    float* dst = g_att + (size_t)(bm + row) * D + h * DK + seg * 16;
#pragma unroll
    for (int q4 = 0; q4 < 4; q4++)
        *(float4*)(dst + q4 * 4) = make_float4(o[q4 * 4 + 0] * inv, o[q4 * 4 + 1] * inv,
                                               o[q4 * 4 + 2] * inv, o[q4 * 4 + 3] * inv);
}

// ---------------- residual + pos + LN2 ----------------
__device__ __forceinline__ float sine_pos_elem(float xe, int i) {
    const float L2_1E4 = 13.287712379549449f;
    int j = i >> 1;
    float dim = exp2f(((float)j / 256.f) * L2_1E4);
    float val = xe / dim;
    return (i & 1) ? cosf(val) : sinf(val);
}

__global__ void k_res_ln2(const float* __restrict__ w, const float* __restrict__ b) {
    int r = blockIdx.x;
    __shared__ float sh[32];
    int i0 = threadIdx.x, i1 = threadIdx.x + 256;
    size_t o = (size_t)r * D;
    float v0, v1;
    if (r < LV) {
        v0 = g_src[o + i0] + g_proj[o + i0] + g_posq[o + i0];
        v1 = g_src[o + i1] + g_proj[o + i1] + g_posq[o + i1];
    } else {
        int tt = r - LV;
        float xe = (float)(tt + 1) / (512.f + 1e-6f) * 6.283185307179586f;
        v0 = g_src[o + i0] + g_src2[o + i0] + sine_pos_elem(xe, i0);
        v1 = g_src[o + i1] + g_src2[o + i1] + sine_pos_elem(xe, i1);
    }
    float s = blk_sum(v0 + v1, sh);
    float s2 = blk_sum(v0 * v0 + v1 * v1, sh);
    float mu = s * (1.f / D);
    float var = s2 * (1.f / D) - mu * mu;
    float inv = rsqrtf(var + 1e-5f);
    g_src[o + i0] = v0;
    g_src[o + i1] = v1;
    g_src2[o + i0] = (v0 - mu) * inv * w[i0] + b[i0];
    g_src2[o + i1] = (v1 - mu) * inv * w[i1] + b[i1];
}

// ---------------- residual + LN3 + output ----------------
__global__ void k_res_ln3(const float* __restrict__ w, const float* __restrict__ b,
                          float* __restrict__ out) {
    int r = blockIdx.x;
    __shared__ float sh[32];
    int i0 = threadIdx.x, i1 = threadIdx.x + 256;
    size_t o = (size_t)r * D;
    float v0 = g_src[o + i0] + g_proj[o + i0];
    float v1 = g_src[o + i1] + g_proj[o + i1];
    float s = blk_sum(v0 + v1, sh);
    float s2 = blk_sum(v0 * v0 + v1 * v1, sh);
    float mu = s * (1.f / D);
    float var = s2 * (1.f / D) - mu * mu;
    float inv = rsqrtf(var + 1e-5f);
    out[o + i0] = (v0 - mu) * inv * w[i0] + b[i0];
    out[o + i1] = (v1 - mu) * inv * w[i1] + b[i1];
}

extern "C" void kernel_launch(void* const* d_in, const int* in_sizes, int n_in,
                              void* d_out, int out_size) {
    const float* src_vid = (const float*)d_in[0];
    const float* src_txt = (const float*)d_in[1];
    const float* ln1_w = (const float*)d_in[2];
    const float* ln1_b = (const float*)d_in[3];
    const float* wq = (const float*)d_in[4];
    const float* bq = (const float*)d_in[5];
    const float* wk = (const float*)d_in[6];
    const float* bk = (const float*)d_in[7];
    const float* wv = (const float*)d_in[8];
    const float* bv = (const float*)d_in[9];
    const float* wo = (const float*)d_in[10];
    const float* bo = (const float*)d_in[11];
    const float* lin1_w = (const float*)d_in[12];
    const float* lin1_b = (const float*)d_in[13];
    const float* lin2_w = (const float*)d_in[14];
    const float* lin2_b = (const float*)d_in[15];
    const float* ln2_w = (const float*)d_in[16];
    const float* ln2_b = (const float*)d_in[17];
    const float* ln3_w = (const float*)d_in[18];
    const float* ln3_b = (const float*)d_in[19];
    const float* learn = (const float*)d_in[20];
    float* out = (float*)d_out;

    cudaFuncSetAttribute(k_flash_chunk, cudaFuncAttributeMaxDynamicSharedMemorySize,
                         FL_SMEM_BYTES);

    k_mask<<<LV, 256>>>(learn);
    k_loss<<<1, 256>>>(out, out_size);
    k_ln1<<<LTOT, 256>>>(src_vid, src_txt, ln1_w, ln1_b);
    k_pos<<<LV, 256>>>(src_vid);

    k_gemm_qkv<<<dim3(D / 64, LV / 128, 3), 256>>>(wq, bq, wk, bk, wv, bv);

    k_vsuf<<<dim3(32, H), 256>>>();
    k_vtrans<<<dim3(LV / 64, H), 256>>>();
    k_flash_chunk<<<dim3(80, H), 256, FL_SMEM_BYTES>>>();
    k_fmerge<<<dim3(32, H), 256>>>();

    k_gemm_o<<<dim3(D / 64, LV / 128), 256>>>(wo, bo);
    k_res_ln2<<<LTOT, 256>>>(ln2_w, ln2_b);

    k_gemm_f1<<<dim3(FF / 64, LTOT / 128), 256>>>(lin1_w, lin1_b);
    k_gemm_f2<<<dim3(D / 64, LTOT / 128), 256>>>(lin2_w, lin2_b);

    k_res_ln3<<<LTOT, 256>>>(ln3_w, ln3_b, out);
}